// round 1
// baseline (speedup 1.0000x reference)
#include <cuda_runtime.h>
#include <math.h>

// ---------------- problem constants ----------------
#define B_     4
#define SEQ    2048
#define D_     512
#define H_     8
#define DH_    64
#define ID_    512
#define MM     266
#define INNER_ 1024
#define KW     31
#define LNUM   6
#define ROWS   (B_*SEQ)     // 8192 token rows
#define RH     (ROWS*H_)    // 65536 (b,n,h) rows

// ---------------- device scratch (no allocations allowed) ----------------
__device__ float g_h  [ROWS*D_];
__device__ float g_q  [ROWS*ID_];
__device__ float g_k  [ROWS*ID_];
__device__ float g_v  [ROWS*ID_];
__device__ float g_qp [RH*MM];
__device__ float g_kp [RH*MM];
__device__ float g_ks [B_*H_*MM];
__device__ float g_ctx[B_*H_*MM*DH_];
__device__ float g_att[ROWS*ID_];
__device__ float g_y  [ROWS*2048];
__device__ float g_glu[ROWS*INNER_];
__device__ float g_dw [ROWS*INNER_];

// ---------------- fp32 tiled GEMM: C = alpha*(A @ W^T) [+bias] [+resid] ----
// A: Mdim x Kdim (row-major, K contiguous)
// W: Ndim x Kdim (row-major, K contiguous)  -> C[i,j] = sum_k A[i,k]*W[j,k]
// Requires: Mdim % 128 == 0, Kdim % 16 == 0. Ndim arbitrary (guarded).
#define BM 128
#define BN 128
#define BK 16

__global__ __launch_bounds__(256)
void gemm_tn(const float* __restrict__ A, const float* __restrict__ W,
             float* __restrict__ C, const float* __restrict__ bias,
             const float* __restrict__ resid,
             int Mdim, int Ndim, int Kdim, float alpha)
{
    __shared__ float As[BK][BM+4];
    __shared__ float Ws[BK][BN+4];

    const int bm = blockIdx.y * BM;
    const int bn = blockIdx.x * BN;
    const int tid = threadIdx.x;

    const int tn8 = (tid & 15) * 8;
    const int tm8 = (tid >> 4) * 8;

    float acc[8][8];
    #pragma unroll
    for (int i = 0; i < 8; i++)
        #pragma unroll
        for (int j = 0; j < 8; j++) acc[i][j] = 0.f;

    for (int k0 = 0; k0 < Kdim; k0 += BK) {
        // load A tile (128x16) and W tile (128x16), 2 float4 each per thread
        #pragma unroll
        for (int u = 0; u < 2; ++u) {
            int i   = tid + u * 256;          // 0..511 float4 slot
            int row = i >> 2;                 // 0..127
            int kc  = (i & 3) << 2;           // 0,4,8,12
            float4 va = *(const float4*)&A[(size_t)(bm + row) * Kdim + k0 + kc];
            As[kc+0][row] = va.x; As[kc+1][row] = va.y;
            As[kc+2][row] = va.z; As[kc+3][row] = va.w;
            int wrow = bn + row;
            float4 vw = make_float4(0.f, 0.f, 0.f, 0.f);
            if (wrow < Ndim)
                vw = *(const float4*)&W[(size_t)wrow * Kdim + k0 + kc];
            Ws[kc+0][row] = vw.x; Ws[kc+1][row] = vw.y;
            Ws[kc+2][row] = vw.z; Ws[kc+3][row] = vw.w;
        }
        __syncthreads();

        #pragma unroll
        for (int kk = 0; kk < BK; ++kk) {
            float4 a0 = *(const float4*)&As[kk][tm8];
            float4 a1 = *(const float4*)&As[kk][tm8 + 4];
            float4 b0 = *(const float4*)&Ws[kk][tn8];
            float4 b1 = *(const float4*)&Ws[kk][tn8 + 4];
            float av[8] = {a0.x,a0.y,a0.z,a0.w,a1.x,a1.y,a1.z,a1.w};
            float bv[8] = {b0.x,b0.y,b0.z,b0.w,b1.x,b1.y,b1.z,b1.w};
            #pragma unroll
            for (int i = 0; i < 8; i++)
                #pragma unroll
                for (int j = 0; j < 8; j++)
                    acc[i][j] += av[i] * bv[j];
        }
        __syncthreads();
    }

    // epilogue
    #pragma unroll
    for (int i = 0; i < 8; i++) {
        int row = bm + tm8 + i;
        #pragma unroll
        for (int j = 0; j < 8; j++) {
            int col = bn + tn8 + j;
            if (col < Ndim) {
                float val = acc[i][j] * alpha;
                if (bias)  val += bias[col];
                if (resid) val += resid[(size_t)row * Ndim + col];
                C[(size_t)row * Ndim + col] = val;
            }
        }
    }
}

// ---------------- LayerNorm over D=512, one block per row -----------------
__global__ void ln_kernel(const float* __restrict__ x, const float* __restrict__ g,
                          const float* __restrict__ b, float* __restrict__ out)
{
    const int r = blockIdx.x;
    const int t = threadIdx.x;   // 128 threads, float4 each -> 512
    const float4 v = ((const float4*)(x + (size_t)r * D_))[t];
    float s  = v.x + v.y + v.z + v.w;
    float ss = v.x*v.x + v.y*v.y + v.z*v.z + v.w*v.w;
    __shared__ float rs[128], rss[128];
    rs[t] = s; rss[t] = ss;
    __syncthreads();
    for (int o = 64; o > 0; o >>= 1) {
        if (t < o) { rs[t] += rs[t+o]; rss[t] += rss[t+o]; }
        __syncthreads();
    }
    const float mu   = rs[0] * (1.f / D_);
    const float var  = rss[0] * (1.f / D_) - mu * mu;
    const float rstd = rsqrtf(var + 1e-5f);
    const float4 gg = ((const float4*)g)[t];
    const float4 bb = ((const float4*)b)[t];
    float4 o4;
    o4.x = (v.x - mu) * rstd * gg.x + bb.x;
    o4.y = (v.y - mu) * rstd * gg.y + bb.y;
    o4.z = (v.z - mu) * rstd * gg.z + bb.z;
    o4.w = (v.w - mu) * rstd * gg.w + bb.w;
    ((float4*)(out + (size_t)r * D_))[t] = o4;
}

// ---------------- FAVOR feature-map postprocess (in-place on dash) --------
// dash row r (266) already holds dn * data @ proj^T. data row r is 64 floats.
__global__ void favor_post(float* __restrict__ dash, const float* __restrict__ data,
                           int isQuery, float ratio)
{
    const int r = blockIdx.x;
    const int t = threadIdx.x;   // 128
    const float* drow = data + (size_t)r * DH_;
    float* prow = dash + (size_t)r * MM;
    __shared__ float red[128];

    float s = 0.f;
    if (t < DH_) { float u = drow[t]; s = u * u; }
    red[t] = s; __syncthreads();
    for (int o = 64; o > 0; o >>= 1) { if (t < o) red[t] += red[t+o]; __syncthreads(); }
    const float diag = red[0] * 0.0625f;   // 0.5*dn^2 = 1/16 exactly
    __syncthreads();

    if (isQuery) {
        float mx = -1e30f;
        for (int m = t; m < MM; m += 128) mx = fmaxf(mx, prow[m]);
        red[t] = mx; __syncthreads();
        for (int o = 64; o > 0; o >>= 1) { if (t < o) red[t] = fmaxf(red[t], red[t+o]); __syncthreads(); }
        mx = red[0];
        for (int m = t; m < MM; m += 128)
            prow[m] = ratio * (expf(prow[m] - diag - mx) + 1e-4f);
    } else {
        for (int m = t; m < MM; m += 128)
            prow[m] = ratio * expf(prow[m] - diag + 1e-4f);
    }
}

// ---------------- k_cumsum: sum kp over n, per (b,h) -----------------------
__global__ void ksum_kernel(const float* __restrict__ kp, float* __restrict__ ks)
{
    const int bh = blockIdx.x;
    const int b = bh >> 3, h = bh & 7;
    const float* base = kp + ((size_t)b * SEQ * H_ + h) * MM;
    for (int m = threadIdx.x; m < MM; m += 256) {
        const float* p = base + m;
        float s0 = 0.f, s1 = 0.f, s2 = 0.f, s3 = 0.f;
        for (int n = 0; n < SEQ; n += 4) {
            s0 += p[(size_t)(n+0) * (H_*MM)];
            s1 += p[(size_t)(n+1) * (H_*MM)];
            s2 += p[(size_t)(n+2) * (H_*MM)];
            s3 += p[(size_t)(n+3) * (H_*MM)];
        }
        ks[bh * MM + m] = (s0 + s1) + (s2 + s3);
    }
}

// ---------------- context: ctx[bh] (266x64) = kp[bh]^T @ v[bh] -------------
__global__ __launch_bounds__(256)
void ctx_kernel(const float* __restrict__ kp, const float* __restrict__ v,
                float* __restrict__ ctx)
{
    const int bh = blockIdx.y;
    const int b = bh >> 3, h = bh & 7;
    const int m0 = blockIdx.x * 64;
    const float* kpb = kp + ((size_t)b * SEQ * H_ + h) * MM;
    const float* vb  = v  + ((size_t)b * SEQ * H_ + h) * DH_;

    __shared__ float As[16][65];  // [n][m]
    __shared__ float Bs[16][65];  // [n][e]
    const int tx = threadIdx.x & 15, ty = threadIdx.x >> 4;

    float acc[4][4];
    #pragma unroll
    for (int i = 0; i < 4; i++)
        #pragma unroll
        for (int j = 0; j < 4; j++) acc[i][j] = 0.f;

    for (int n0 = 0; n0 < SEQ; n0 += 16) {
        for (int i = threadIdx.x; i < 16 * 64; i += 256) {
            int nn = i >> 6, mm = i & 63;
            int gm = m0 + mm;
            As[nn][mm] = (gm < MM) ? kpb[(size_t)(n0 + nn) * (H_*MM) + gm] : 0.f;
            Bs[nn][mm] = vb[(size_t)(n0 + nn) * (H_*DH_) + mm];
        }
        __syncthreads();
        #pragma unroll
        for (int kk = 0; kk < 16; kk++) {
            float a[4], bb[4];
            #pragma unroll
            for (int i = 0; i < 4; i++) a[i] = As[kk][ty*4 + i];
            #pragma unroll
            for (int j = 0; j < 4; j++) bb[j] = Bs[kk][tx*4 + j];
            #pragma unroll
            for (int i = 0; i < 4; i++)
                #pragma unroll
                for (int j = 0; j < 4; j++) acc[i][j] += a[i] * bb[j];
        }
        __syncthreads();
    }

    float* cb = ctx + (size_t)bh * MM * DH_;
    #pragma unroll
    for (int i = 0; i < 4; i++) {
        int m = m0 + ty*4 + i;
        if (m < MM) {
            #pragma unroll
            for (int j = 0; j < 4; j++)
                cb[(size_t)m * DH_ + tx*4 + j] = acc[i][j];
        }
    }
}

// ---------------- attention out: out[r,:] = dinv * qp[r,:] @ ctx[bh] -------
__global__ void attn_out_kernel(const float* __restrict__ qp, const float* __restrict__ ks,
                                const float* __restrict__ ctx, float* __restrict__ out)
{
    const int r = blockIdx.x;          // (b*2048+n)*8 + h
    const int t = threadIdx.x;         // 64
    const int h = r & 7;
    const int b = r >> 14;
    const int bh = (b << 3) | h;

    __shared__ float sq[MM];
    __shared__ float red[64];
    const float* qrow = qp + (size_t)r * MM;
    const float* kv   = ks + bh * MM;

    float part = 0.f;
    for (int m = t; m < MM; m += 64) {
        float qv = qrow[m];
        sq[m] = qv;
        part += qv * kv[m];
    }
    red[t] = part; __syncthreads();
    for (int o = 32; o > 0; o >>= 1) { if (t < o) red[t] += red[t+o]; __syncthreads(); }
    const float dinv = 1.f / (red[0] + 1e-8f);

    const float* cb = ctx + (size_t)bh * MM * DH_;
    float acc = 0.f;
    #pragma unroll 2
    for (int m = 0; m < MM; m++) acc += sq[m] * cb[(size_t)m * DH_ + t];
    out[(size_t)r * DH_ + t] = acc * dinv;
}

// ---------------- GLU: a * sigmoid(g) ---------------------------------------
__global__ void glu_kernel(const float* __restrict__ y, float* __restrict__ out)
{
    size_t idx = (size_t)blockIdx.x * 256 + threadIdx.x;  // ROWS*INNER_
    size_t i = idx >> 10;
    int c = (int)(idx & 1023);
    float a = y[i * 2048 + c];
    float g = y[i * 2048 + 1024 + c];
    out[idx] = a / (1.f + expf(-g));
}

// ---------------- depthwise conv (K=31, pad 15) + SiLU ----------------------
__global__ void dwconv_kernel(const float* __restrict__ gin, const float* __restrict__ w,
                              const float* __restrict__ bias, float* __restrict__ out)
{
    __shared__ float ws[256 * KW];   // weights for this block's 256 channels
    const size_t base = (size_t)blockIdx.x * 256;
    const int c0 = (int)(base & 1023);
    for (int i = threadIdx.x; i < 256 * KW; i += 256)
        ws[i] = w[(size_t)c0 * KW + i];
    __syncthreads();

    const size_t idx = base + threadIdx.x;
    const int c = (int)(idx & 1023);
    const int n = (int)((idx >> 10) & 2047);
    const int b = (int)(idx >> 21);

    float acc = bias[c];
    const float* col = gin + (((size_t)b * SEQ) << 10) + c;
    #pragma unroll
    for (int k = 0; k < KW; k++) {
        int nn = n + k - 15;
        if ((unsigned)nn < SEQ)
            acc += col[(size_t)nn << 10] * ws[threadIdx.x * KW + k];
    }
    out[idx] = acc / (1.f + expf(-acc));   // SiLU
}

// ---------------- host orchestration ----------------------------------------
static inline void run_gemm(const float* A, const float* W, float* C,
                            const float* bias, const float* resid,
                            int Mdim, int Ndim, int Kdim, float alpha)
{
    dim3 grid((Ndim + BN - 1) / BN, (Mdim + BM - 1) / BM);
    gemm_tn<<<grid, 256>>>(A, W, C, bias, resid, Mdim, Ndim, Kdim, alpha);
}

extern "C" void kernel_launch(void* const* d_in, const int* in_sizes, int n_in,
                              void* d_out, int out_size)
{
    const float* x    = (const float*)d_in[0];
    const float* ln1g = (const float*)d_in[1];
    const float* ln1b = (const float*)d_in[2];
    const float* wq   = (const float*)d_in[3];
    const float* bq   = (const float*)d_in[4];
    const float* wk   = (const float*)d_in[5];
    const float* bk   = (const float*)d_in[6];
    const float* wv   = (const float*)d_in[7];
    const float* bv   = (const float*)d_in[8];
    const float* wo   = (const float*)d_in[9];
    const float* bo   = (const float*)d_in[10];
    const float* proj = (const float*)d_in[11];
    const float* ln2g = (const float*)d_in[12];
    const float* ln2b = (const float*)d_in[13];
    const float* pw1w = (const float*)d_in[14];
    const float* pw1b = (const float*)d_in[15];
    const float* dww  = (const float*)d_in[16];
    const float* dwb  = (const float*)d_in[17];
    const float* pw2w = (const float*)d_in[18];
    const float* pw2b = (const float*)d_in[19];
    float* xo = (float*)d_out;

    float *h, *q, *k, *v, *qp, *kp, *ks, *ctx, *att, *y, *glu, *dw;
    cudaGetSymbolAddress((void**)&h,   g_h);
    cudaGetSymbolAddress((void**)&q,   g_q);
    cudaGetSymbolAddress((void**)&k,   g_k);
    cudaGetSymbolAddress((void**)&v,   g_v);
    cudaGetSymbolAddress((void**)&qp,  g_qp);
    cudaGetSymbolAddress((void**)&kp,  g_kp);
    cudaGetSymbolAddress((void**)&ks,  g_ks);
    cudaGetSymbolAddress((void**)&ctx, g_ctx);
    cudaGetSymbolAddress((void**)&att, g_att);
    cudaGetSymbolAddress((void**)&y,   g_y);
    cudaGetSymbolAddress((void**)&glu, g_glu);
    cudaGetSymbolAddress((void**)&dw,  g_dw);

    cudaMemcpyAsync(xo, x, (size_t)ROWS * D_ * sizeof(float),
                    cudaMemcpyDeviceToDevice);

    const float dn    = (float)(1.0 / sqrt(sqrt(64.0)));   // 64^-0.25
    const float ratio = (float)(1.0 / sqrt(266.0));        // M^-0.5

    for (int l = 0; l < LNUM; l++) {
        // LN1
        ln_kernel<<<ROWS, 128>>>(xo, ln1g + (size_t)l*D_, ln1b + (size_t)l*D_, h);
        // QKV
        run_gemm(h, wq + (size_t)l*ID_*D_, q, bq + (size_t)l*ID_, nullptr, ROWS, ID_, D_, 1.f);
        run_gemm(h, wk + (size_t)l*ID_*D_, k, bk + (size_t)l*ID_, nullptr, ROWS, ID_, D_, 1.f);
        run_gemm(h, wv + (size_t)l*ID_*D_, v, bv + (size_t)l*ID_, nullptr, ROWS, ID_, D_, 1.f);
        // FAVOR feature maps: dash = dn * data @ proj^T, then exp postprocess
        run_gemm(q, proj + (size_t)l*MM*DH_, qp, nullptr, nullptr, RH, MM, DH_, dn);
        run_gemm(k, proj + (size_t)l*MM*DH_, kp, nullptr, nullptr, RH, MM, DH_, dn);
        favor_post<<<RH, 128>>>(qp, q, 1, ratio);
        favor_post<<<RH, 128>>>(kp, k, 0, ratio);
        // linear attention
        ksum_kernel<<<B_*H_, 256>>>(kp, ks);
        dim3 cg((MM + 63) / 64, B_*H_);
        ctx_kernel<<<cg, 256>>>(kp, v, ctx);
        attn_out_kernel<<<RH, 64>>>(qp, ks, ctx, att);
        // output projection + residual (in-place on xo)
        run_gemm(att, wo + (size_t)l*ID_*D_, xo, bo + (size_t)l*D_, xo, ROWS, D_, ID_, 1.f);
        // LN2 + conv-FFN
        ln_kernel<<<ROWS, 128>>>(xo, ln2g + (size_t)l*D_, ln2b + (size_t)l*D_, h);
        run_gemm(h, pw1w + (size_t)l*2048*D_, y, pw1b + (size_t)l*2048, nullptr, ROWS, 2048, D_, 1.f);
        glu_kernel<<<(ROWS*INNER_)/256, 256>>>(y, glu);
        dwconv_kernel<<<(ROWS*INNER_)/256, 256>>>(glu, dww + (size_t)l*INNER_*KW,
                                                  dwb + (size_t)l*INNER_, dw);
        run_gemm(dw, pw2w + (size_t)l*D_*INNER_, xo, pw2b + (size_t)l*D_, xo, ROWS, D_, INNER_, 1.f);
    }
}

// round 3
// speedup vs baseline: 1.4823x; 1.4823x over previous
#include <cuda_runtime.h>
#include <cuda_bf16.h>
#include <math.h>
#include <stdint.h>

// ---------------- problem constants ----------------
#define B_     4
#define SEQ    2048
#define D_     512
#define H_     8
#define DH_    64
#define ID_    512
#define MM     266
#define INNER_ 1024
#define KW     31
#define LNUM   6
#define ROWS   (B_*SEQ)     // 8192 token rows
#define RH     (ROWS*H_)    // 65536 (b,n,h) rows

// ---------------- device scratch (no allocations allowed) ----------------
__device__ float g_h  [ROWS*D_];
__device__ float g_q  [ROWS*ID_];
__device__ float g_k  [ROWS*ID_];
__device__ float g_v  [ROWS*ID_];
__device__ float g_qp [RH*MM];
__device__ float g_kp [RH*MM];
__device__ float g_ks [B_*H_*MM];
__device__ float g_ctx[B_*H_*MM*DH_];
__device__ float g_att[ROWS*ID_];
__device__ float g_y  [ROWS*2048];
__device__ float g_glu[ROWS*INNER_];
__device__ float g_dw [ROWS*INNER_];

// ======================================================================
// bf16-split (3-MMA) tensor-core GEMM:  C = alpha*(A @ W^T) [+bias][+resid]
// A: Mdim x Kdim row-major (Mdim%128==0, Kdim%32==0)
// W: Ndim x Kdim row-major (Ndim arbitrary, guarded)
// Each fp32 operand is split x = hi + lo (two bf16); D += Ah*Bh + Ah*Bl + Al*Bh
// ======================================================================

__device__ __forceinline__ uint32_t pk2(__nv_bfloat16 a, __nv_bfloat16 b) {
    __nv_bfloat162 t = __halves2bfloat162(a, b);
    return *reinterpret_cast<uint32_t*>(&t);
}
__device__ __forceinline__ uint32_t pkf2(float a, float b) {
    __nv_bfloat162 t = __floats2bfloat162_rn(a, b);
    return *reinterpret_cast<uint32_t*>(&t);
}

__device__ __forceinline__ void ldm4(uint32_t* r, uint32_t addr) {
    asm volatile("ldmatrix.sync.aligned.m8n8.x4.shared.b16 {%0,%1,%2,%3}, [%4];\n"
                 : "=r"(r[0]), "=r"(r[1]), "=r"(r[2]), "=r"(r[3]) : "r"(addr));
}

__device__ __forceinline__ void mma_bf16(float* c, const uint32_t* a, const uint32_t* b) {
    asm volatile(
        "mma.sync.aligned.m16n8k16.row.col.f32.bf16.bf16.f32 "
        "{%0,%1,%2,%3}, {%4,%5,%6,%7}, {%8,%9}, {%0,%1,%2,%3};\n"
        : "+f"(c[0]), "+f"(c[1]), "+f"(c[2]), "+f"(c[3])
        : "r"(a[0]), "r"(a[1]), "r"(a[2]), "r"(a[3]), "r"(b[0]), "r"(b[1]));
}

// padded bf16 k-stride: 40 elems = 80 bytes/row -> every ldmatrix row address
// is 16B-aligned (80 = 5*16) and the 8 rows hit disjoint bank quartets.
#define ASTR 40

__global__ __launch_bounds__(256, 1)
void gemm_bf16x3(const float* __restrict__ A, const float* __restrict__ W,
                 float* __restrict__ C, const float* __restrict__ bias,
                 const float* __restrict__ resid,
                 int Mdim, int Ndim, int Kdim, float alpha)
{
    __shared__ __align__(16) __nv_bfloat16 As[2][128][ASTR];
    __shared__ __align__(16) __nv_bfloat16 Bs[2][128][ASTR];

    const int tid  = threadIdx.x;
    const int lane = tid & 31;
    const int warp = tid >> 5;
    const int wm = (warp & 1) * 64;    // warp tile 64x32
    const int wn = (warp >> 1) * 32;
    const int bm = blockIdx.y * 128;
    const int bn = blockIdx.x * 128;

    // global-load mapping: each thread 4 float4 per matrix per ktile
    const int r0 = tid >> 3;           // row base (0..31), +u*32
    const int kk = (tid & 7) * 4;      // k offset within 32

    float4 pa[4], pb[4];

    float acc[4][4][4];
    #pragma unroll
    for (int i = 0; i < 4; i++)
        #pragma unroll
        for (int j = 0; j < 4; j++)
            #pragma unroll
            for (int t = 0; t < 4; t++) acc[i][j][t] = 0.f;

    // ldmatrix per-lane source coordinates
    const int a_m = lane & 15;
    const int a_k = (lane >> 4) << 3;
    const int b_n = (lane & 7) | ((lane & 16) >> 1);
    const int b_k = lane & 8;

    uint32_t sA = (uint32_t)__cvta_generic_to_shared(&As[0][0][0]);
    uint32_t sB = (uint32_t)__cvta_generic_to_shared(&Bs[0][0][0]);
    const uint32_t splitOff = 128 * ASTR * 2;   // bytes between hi and lo planes

    const int KT = Kdim >> 5;

    // prefetch ktile 0
    #pragma unroll
    for (int u = 0; u < 4; u++)
        pa[u] = *(const float4*)&A[(size_t)(bm + r0 + u*32) * Kdim + kk];
    #pragma unroll
    for (int u = 0; u < 4; u++) {
        int wrow = bn + r0 + u*32;
        pb[u] = (wrow < Ndim) ? *(const float4*)&W[(size_t)wrow * Kdim + kk]
                              : make_float4(0.f, 0.f, 0.f, 0.f);
    }

    for (int kt = 0; kt < KT; kt++) {
        // convert + store to smem (hi and lo planes)
        #pragma unroll
        for (int u = 0; u < 4; u++) {
            int row = r0 + u*32;
            {
                float4 v = pa[u];
                __nv_bfloat16 h0 = __float2bfloat16(v.x), h1 = __float2bfloat16(v.y),
                              h2 = __float2bfloat16(v.z), h3 = __float2bfloat16(v.w);
                uint2 hi, lo;
                hi.x = pk2(h0, h1); hi.y = pk2(h2, h3);
                lo.x = pkf2(v.x - __bfloat162float(h0), v.y - __bfloat162float(h1));
                lo.y = pkf2(v.z - __bfloat162float(h2), v.w - __bfloat162float(h3));
                *(uint2*)&As[0][row][kk] = hi;
                *(uint2*)&As[1][row][kk] = lo;
            }
            {
                float4 v = pb[u];
                __nv_bfloat16 h0 = __float2bfloat16(v.x), h1 = __float2bfloat16(v.y),
                              h2 = __float2bfloat16(v.z), h3 = __float2bfloat16(v.w);
                uint2 hi, lo;
                hi.x = pk2(h0, h1); hi.y = pk2(h2, h3);
                lo.x = pkf2(v.x - __bfloat162float(h0), v.y - __bfloat162float(h1));
                lo.y = pkf2(v.z - __bfloat162float(h2), v.w - __bfloat162float(h3));
                *(uint2*)&Bs[0][row][kk] = hi;
                *(uint2*)&Bs[1][row][kk] = lo;
            }
        }
        __syncthreads();

        // prefetch next ktile while computing this one
        if (kt + 1 < KT) {
            #pragma unroll
            for (int u = 0; u < 4; u++)
                pa[u] = *(const float4*)&A[(size_t)(bm + r0 + u*32) * Kdim + (kt+1)*32 + kk];
            #pragma unroll
            for (int u = 0; u < 4; u++) {
                int wrow = bn + r0 + u*32;
                pb[u] = (wrow < Ndim) ? *(const float4*)&W[(size_t)wrow * Kdim + (kt+1)*32 + kk]
                                      : make_float4(0.f, 0.f, 0.f, 0.f);
            }
        }

        #pragma unroll
        for (int ks = 0; ks < 2; ks++) {
            uint32_t bh[4][2], bl[4][2];
            #pragma unroll
            for (int p = 0; p < 2; p++) {
                uint32_t addr = sB + (uint32_t)(((wn + p*16 + b_n) * ASTR) + ks*16 + b_k) * 2;
                uint32_t r[4];
                ldm4(r, addr);
                bh[2*p][0] = r[0]; bh[2*p][1] = r[1];
                bh[2*p+1][0] = r[2]; bh[2*p+1][1] = r[3];
                ldm4(r, addr + splitOff);
                bl[2*p][0] = r[0]; bl[2*p][1] = r[1];
                bl[2*p+1][0] = r[2]; bl[2*p+1][1] = r[3];
            }
            #pragma unroll
            for (int mt = 0; mt < 4; mt++) {
                uint32_t ah[4], al[4];
                uint32_t addr = sA + (uint32_t)(((wm + mt*16 + a_m) * ASTR) + ks*16 + a_k) * 2;
                ldm4(ah, addr);
                ldm4(al, addr + splitOff);
                #pragma unroll
                for (int nt = 0; nt < 4; nt++) {
                    mma_bf16(acc[mt][nt], ah, bh[nt]);
                    mma_bf16(acc[mt][nt], ah, bl[nt]);
                    mma_bf16(acc[mt][nt], al, bh[nt]);
                }
            }
        }
        __syncthreads();
    }

    // epilogue
    const int gr = lane >> 2;
    const int gc = (lane & 3) * 2;
    #pragma unroll
    for (int mt = 0; mt < 4; mt++) {
        #pragma unroll
        for (int nt = 0; nt < 4; nt++) {
            const float* cp = acc[mt][nt];
            int row = bm + wm + mt*16 + gr;
            int col = bn + wn + nt*8 + gc;
            #pragma unroll
            for (int half = 0; half < 2; half++) {
                int rr = row + half*8;
                #pragma unroll
                for (int j = 0; j < 2; j++) {
                    int cc = col + j;
                    if (cc < Ndim) {
                        float val = cp[half*2 + j] * alpha;
                        if (bias)  val += bias[cc];
                        if (resid) val += resid[(size_t)rr * Ndim + cc];
                        C[(size_t)rr * Ndim + cc] = val;
                    }
                }
            }
        }
    }
}

// ---------------- LayerNorm over D=512, one block per row -----------------
__global__ void ln_kernel(const float* __restrict__ x, const float* __restrict__ g,
                          const float* __restrict__ b, float* __restrict__ out)
{
    const int r = blockIdx.x;
    const int t = threadIdx.x;   // 128 threads, float4 each -> 512
    const float4 v = ((const float4*)(x + (size_t)r * D_))[t];
    float s  = v.x + v.y + v.z + v.w;
    float ss = v.x*v.x + v.y*v.y + v.z*v.z + v.w*v.w;
    __shared__ float rs[128], rss[128];
    rs[t] = s; rss[t] = ss;
    __syncthreads();
    for (int o = 64; o > 0; o >>= 1) {
        if (t < o) { rs[t] += rs[t+o]; rss[t] += rss[t+o]; }
        __syncthreads();
    }
    const float mu   = rs[0] * (1.f / D_);
    const float var  = rss[0] * (1.f / D_) - mu * mu;
    const float rstd = rsqrtf(var + 1e-5f);
    const float4 gg = ((const float4*)g)[t];
    const float4 bb = ((const float4*)b)[t];
    float4 o4;
    o4.x = (v.x - mu) * rstd * gg.x + bb.x;
    o4.y = (v.y - mu) * rstd * gg.y + bb.y;
    o4.z = (v.z - mu) * rstd * gg.z + bb.z;
    o4.w = (v.w - mu) * rstd * gg.w + bb.w;
    ((float4*)(out + (size_t)r * D_))[t] = o4;
}

// ---------------- FAVOR feature-map postprocess (in-place on dash) --------
__global__ void favor_post(float* __restrict__ dash, const float* __restrict__ data,
                           int isQuery, float ratio)
{
    const int r = blockIdx.x;
    const int t = threadIdx.x;   // 128
    const float* drow = data + (size_t)r * DH_;
    float* prow = dash + (size_t)r * MM;
    __shared__ float red[128];

    float s = 0.f;
    if (t < DH_) { float u = drow[t]; s = u * u; }
    red[t] = s; __syncthreads();
    for (int o = 64; o > 0; o >>= 1) { if (t < o) red[t] += red[t+o]; __syncthreads(); }
    const float diag = red[0] * 0.0625f;   // 0.5*dn^2 = 1/16 exactly
    __syncthreads();

    if (isQuery) {
        float mx = -1e30f;
        for (int m = t; m < MM; m += 128) mx = fmaxf(mx, prow[m]);
        red[t] = mx; __syncthreads();
        for (int o = 64; o > 0; o >>= 1) { if (t < o) red[t] = fmaxf(red[t], red[t+o]); __syncthreads(); }
        mx = red[0];
        for (int m = t; m < MM; m += 128)
            prow[m] = ratio * (expf(prow[m] - diag - mx) + 1e-4f);
    } else {
        for (int m = t; m < MM; m += 128)
            prow[m] = ratio * expf(prow[m] - diag + 1e-4f);
    }
}

// ---------------- k_cumsum: sum kp over n, per (b,h) -----------------------
__global__ void ksum_kernel(const float* __restrict__ kp, float* __restrict__ ks)
{
    const int bh = blockIdx.x;
    const int b = bh >> 3, h = bh & 7;
    const float* base = kp + ((size_t)b * SEQ * H_ + h) * MM;
    for (int m = threadIdx.x; m < MM; m += 256) {
        const float* p = base + m;
        float s0 = 0.f, s1 = 0.f, s2 = 0.f, s3 = 0.f;
        for (int n = 0; n < SEQ; n += 4) {
            s0 += p[(size_t)(n+0) * (H_*MM)];
            s1 += p[(size_t)(n+1) * (H_*MM)];
            s2 += p[(size_t)(n+2) * (H_*MM)];
            s3 += p[(size_t)(n+3) * (H_*MM)];
        }
        ks[bh * MM + m] = (s0 + s1) + (s2 + s3);
    }
}

// ---------------- context: ctx[bh] (266x64) = kp[bh]^T @ v[bh] -------------
__global__ __launch_bounds__(256)
void ctx_kernel(const float* __restrict__ kp, const float* __restrict__ v,
                float* __restrict__ ctx)
{
    const int bh = blockIdx.y;
    const int b = bh >> 3, h = bh & 7;
    const int m0 = blockIdx.x * 64;
    const float* kpb = kp + ((size_t)b * SEQ * H_ + h) * MM;
    const float* vb  = v  + ((size_t)b * SEQ * H_ + h) * DH_;

    __shared__ float As[16][65];  // [n][m]
    __shared__ float Bs[16][65];  // [n][e]
    const int tx = threadIdx.x & 15, ty = threadIdx.x >> 4;

    float acc[4][4];
    #pragma unroll
    for (int i = 0; i < 4; i++)
        #pragma unroll
        for (int j = 0; j < 4; j++) acc[i][j] = 0.f;

    for (int n0 = 0; n0 < SEQ; n0 += 16) {
        for (int i = threadIdx.x; i < 16 * 64; i += 256) {
            int nn = i >> 6, mm = i & 63;
            int gm = m0 + mm;
            As[nn][mm] = (gm < MM) ? kpb[(size_t)(n0 + nn) * (H_*MM) + gm] : 0.f;
            Bs[nn][mm] = vb[(size_t)(n0 + nn) * (H_*DH_) + mm];
        }
        __syncthreads();
        #pragma unroll
        for (int kk = 0; kk < 16; kk++) {
            float a[4], bb[4];
            #pragma unroll
            for (int i = 0; i < 4; i++) a[i] = As[kk][ty*4 + i];
            #pragma unroll
            for (int j = 0; j < 4; j++) bb[j] = Bs[kk][tx*4 + j];
            #pragma unroll
            for (int i = 0; i < 4; i++)
                #pragma unroll
                for (int j = 0; j < 4; j++) acc[i][j] += a[i] * bb[j];
        }
        __syncthreads();
    }

    float* cb = ctx + (size_t)bh * MM * DH_;
    #pragma unroll
    for (int i = 0; i < 4; i++) {
        int m = m0 + ty*4 + i;
        if (m < MM) {
            #pragma unroll
            for (int j = 0; j < 4; j++)
                cb[(size_t)m * DH_ + tx*4 + j] = acc[i][j];
        }
    }
}

// ---------------- attention out, smem-tiled with ctx reuse ------------------
// block: 32 rows (same bh) x 64 head-dims. Folds the d_inv reduction.
__global__ __launch_bounds__(256)
void attn_out2(const float* __restrict__ qp, const float* __restrict__ ks,
               const float* __restrict__ ctx, float* __restrict__ out)
{
    const int bh = blockIdx.y;
    const int b = bh >> 3, h = bh & 7;
    const int n0 = blockIdx.x * 32;
    const int t = threadIdx.x;
    const int ri = t >> 3;         // 0..31 row within chunk
    const int e0 = (t & 7) * 8;    // 8 output dims

    __shared__ __align__(16) float cs[64][68];
    __shared__ float qs[32][65];
    __shared__ float dsum[32];

    if (t < 32) dsum[t] = 0.f;
    float acc[8];
    #pragma unroll
    for (int j = 0; j < 8; j++) acc[j] = 0.f;

    const float* ksb = ks + bh * MM;
    const float4 z4 = make_float4(0.f, 0.f, 0.f, 0.f);

    for (int m0 = 0; m0 < MM; m0 += 64) {
        // ctx chunk: 64x64 floats
        #pragma unroll
        for (int u = 0; u < 4; u++) {
            int f = t + u*256;
            int mm = f >> 4;
            int ee = (f & 15) * 4;
            int gm = m0 + mm;
            float4 v = (gm < MM) ? *(const float4*)&ctx[((size_t)bh * MM + gm) * DH_ + ee] : z4;
            *(float4*)&cs[mm][ee] = v;
        }
        // qp chunk: 32 rows x 64 m
        #pragma unroll
        for (int u = 0; u < 4; u++) {
            int f = t + u*256;          // float2 slots
            int rr = f >> 5;
            int mm = (f & 31) * 2;
            int gm = m0 + mm;
            float2 v = make_float2(0.f, 0.f);
            if (gm < MM) {
                const float* qrow = qp + ((size_t)(b * SEQ + n0 + rr) * H_ + h) * MM;
                v.x = qrow[gm]; v.y = qrow[gm + 1];
            }
            qs[rr][mm] = v.x; qs[rr][mm + 1] = v.y;
        }
        __syncthreads();

        if (t < 32) {
            float s = 0.f;
            for (int mm = 0; mm < 64; mm++) {
                int gm = m0 + mm;
                if (gm < MM) s += qs[t][mm] * ksb[gm];
            }
            dsum[t] += s;
        }

        #pragma unroll 4
        for (int mm = 0; mm < 64; mm++) {
            float qv = qs[ri][mm];
            float4 c0 = *(const float4*)&cs[mm][e0];
            float4 c1 = *(const float4*)&cs[mm][e0 + 4];
            acc[0] += qv * c0.x; acc[1] += qv * c0.y;
            acc[2] += qv * c0.z; acc[3] += qv * c0.w;
            acc[4] += qv * c1.x; acc[5] += qv * c1.y;
            acc[6] += qv * c1.z; acc[7] += qv * c1.w;
        }
        __syncthreads();
    }

    const float dinv = 1.f / (dsum[ri] + 1e-8f);
    float* orow = out + ((size_t)(b * SEQ + n0 + ri) * H_ + h) * DH_ + e0;
    float4 o0 = make_float4(acc[0]*dinv, acc[1]*dinv, acc[2]*dinv, acc[3]*dinv);
    float4 o1 = make_float4(acc[4]*dinv, acc[5]*dinv, acc[6]*dinv, acc[7]*dinv);
    *(float4*)&orow[0] = o0;
    *(float4*)&orow[4] = o1;
}

// ---------------- GLU: a * sigmoid(g) ---------------------------------------
__global__ void glu_kernel(const float* __restrict__ y, float* __restrict__ out)
{
    size_t idx = (size_t)blockIdx.x * 256 + threadIdx.x;  // ROWS*INNER_
    size_t i = idx >> 10;
    int c = (int)(idx & 1023);
    float a = y[i * 2048 + c];
    float g = y[i * 2048 + 1024 + c];
    out[idx] = a / (1.f + expf(-g));
}

// ---------------- depthwise conv (K=31, pad 15) + SiLU ----------------------
__global__ void dwconv_kernel(const float* __restrict__ gin, const float* __restrict__ w,
                              const float* __restrict__ bias, float* __restrict__ out)
{
    __shared__ float ws[256 * KW];
    const size_t base = (size_t)blockIdx.x * 256;
    const int c0 = (int)(base & 1023);
    for (int i = threadIdx.x; i < 256 * KW; i += 256)
        ws[i] = w[(size_t)c0 * KW + i];
    __syncthreads();

    const size_t idx = base + threadIdx.x;
    const int c = (int)(idx & 1023);
    const int n = (int)((idx >> 10) & 2047);
    const int b = (int)(idx >> 21);

    float acc = bias[c];
    const float* col = gin + (((size_t)b * SEQ) << 10) + c;
    #pragma unroll
    for (int k = 0; k < KW; k++) {
        int nn = n + k - 15;
        if ((unsigned)nn < SEQ)
            acc += col[(size_t)nn << 10] * ws[threadIdx.x * KW + k];
    }
    out[idx] = acc / (1.f + expf(-acc));   // SiLU
}

// ---------------- host orchestration ----------------------------------------
static inline void run_gemm(const float* A, const float* W, float* C,
                            const float* bias, const float* resid,
                            int Mdim, int Ndim, int Kdim, float alpha)
{
    dim3 grid((Ndim + 127) / 128, Mdim / 128);
    gemm_bf16x3<<<grid, 256>>>(A, W, C, bias, resid, Mdim, Ndim, Kdim, alpha);
}

extern "C" void kernel_launch(void* const* d_in, const int* in_sizes, int n_in,
                              void* d_out, int out_size)
{
    const float* x    = (const float*)d_in[0];
    const float* ln1g = (const float*)d_in[1];
    const float* ln1b = (const float*)d_in[2];
    const float* wq   = (const float*)d_in[3];
    const float* bq   = (const float*)d_in[4];
    const float* wk   = (const float*)d_in[5];
    const float* bk   = (const float*)d_in[6];
    const float* wv   = (const float*)d_in[7];
    const float* bv   = (const float*)d_in[8];
    const float* wo   = (const float*)d_in[9];
    const float* bo   = (const float*)d_in[10];
    const float* proj = (const float*)d_in[11];
    const float* ln2g = (const float*)d_in[12];
    const float* ln2b = (const float*)d_in[13];
    const float* pw1w = (const float*)d_in[14];
    const float* pw1b = (const float*)d_in[15];
    const float* dww  = (const float*)d_in[16];
    const float* dwb  = (const float*)d_in[17];
    const float* pw2w = (const float*)d_in[18];
    const float* pw2b = (const float*)d_in[19];
    float* xo = (float*)d_out;

    float *h, *q, *k, *v, *qp, *kp, *ks, *ctx, *att, *y, *glu, *dw;
    cudaGetSymbolAddress((void**)&h,   g_h);
    cudaGetSymbolAddress((void**)&q,   g_q);
    cudaGetSymbolAddress((void**)&k,   g_k);
    cudaGetSymbolAddress((void**)&v,   g_v);
    cudaGetSymbolAddress((void**)&qp,  g_qp);
    cudaGetSymbolAddress((void**)&kp,  g_kp);
    cudaGetSymbolAddress((void**)&ks,  g_ks);
    cudaGetSymbolAddress((void**)&ctx, g_ctx);
    cudaGetSymbolAddress((void**)&att, g_att);
    cudaGetSymbolAddress((void**)&y,   g_y);
    cudaGetSymbolAddress((void**)&glu, g_glu);
    cudaGetSymbolAddress((void**)&dw,  g_dw);

    cudaMemcpyAsync(xo, x, (size_t)ROWS * D_ * sizeof(float),
                    cudaMemcpyDeviceToDevice);

    const float dn    = (float)(1.0 / sqrt(sqrt(64.0)));   // 64^-0.25
    const float ratio = (float)(1.0 / sqrt(266.0));        // M^-0.5

    for (int l = 0; l < LNUM; l++) {
        // LN1
        ln_kernel<<<ROWS, 128>>>(xo, ln1g + (size_t)l*D_, ln1b + (size_t)l*D_, h);
        // QKV
        run_gemm(h, wq + (size_t)l*ID_*D_, q, bq + (size_t)l*ID_, nullptr, ROWS, ID_, D_, 1.f);
        run_gemm(h, wk + (size_t)l*ID_*D_, k, bk + (size_t)l*ID_, nullptr, ROWS, ID_, D_, 1.f);
        run_gemm(h, wv + (size_t)l*ID_*D_, v, bv + (size_t)l*ID_, nullptr, ROWS, ID_, D_, 1.f);
        // FAVOR feature maps: dash = dn * data @ proj^T, then exp postprocess
        run_gemm(q, proj + (size_t)l*MM*DH_, qp, nullptr, nullptr, RH, MM, DH_, dn);
        run_gemm(k, proj + (size_t)l*MM*DH_, kp, nullptr, nullptr, RH, MM, DH_, dn);
        favor_post<<<RH, 128>>>(qp, q, 1, ratio);
        favor_post<<<RH, 128>>>(kp, k, 0, ratio);
        // linear attention
        ksum_kernel<<<B_*H_, 256>>>(kp, ks);
        dim3 cg((MM + 63) / 64, B_*H_);
        ctx_kernel<<<cg, 256>>>(kp, v, ctx);
        dim3 ag(SEQ / 32, B_*H_);
        attn_out2<<<ag, 256>>>(qp, ks, ctx, att);
        // output projection + residual (in-place on xo)
        run_gemm(att, wo + (size_t)l*ID_*D_, xo, bo + (size_t)l*D_, xo, ROWS, D_, ID_, 1.f);
        // LN2 + conv-FFN
        ln_kernel<<<ROWS, 128>>>(xo, ln2g + (size_t)l*D_, ln2b + (size_t)l*D_, h);
        run_gemm(h, pw1w + (size_t)l*2048*D_, y, pw1b + (size_t)l*2048, nullptr, ROWS, 2048, D_, 1.f);
        glu_kernel<<<(ROWS*INNER_)/256, 256>>>(y, glu);
        dwconv_kernel<<<(ROWS*INNER_)/256, 256>>>(glu, dww + (size_t)l*INNER_*KW,
                                                  dwb + (size_t)l*INNER_, dw);
        run_gemm(dw, pw2w + (size_t)l*D_*INNER_, xo, pw2b + (size_t)l*D_, xo, ROWS, D_, INNER_, 1.f);
    }
}

// round 4
// speedup vs baseline: 1.9575x; 1.3206x over previous
#include <cuda_runtime.h>
#include <cuda_bf16.h>
#include <math.h>
#include <stdint.h>

// ---------------- problem constants ----------------
#define B_     4
#define SEQ    2048
#define D_     512
#define H_     8
#define DH_    64
#define ID_    512
#define MM     266
#define MMP    272          // padded feature dim (16B-aligned rows)
#define INNER_ 1024
#define KW     31
#define LNUM   6
#define ROWS   (B_*SEQ)     // 8192 token rows
#define RH     (ROWS*H_)    // 65536 (b,n,h) rows
#define NBH    (B_*H_)      // 32

// ---------------- device scratch (no allocations allowed) ----------------
__device__ float g_h   [ROWS*D_];
__device__ float g_q   [ROWS*ID_];
__device__ float g_k   [ROWS*ID_];
__device__ float g_v   [ROWS*ID_];
__device__ float g_qp  [NBH*SEQ*MMP];   // [bh][n][m]
__device__ float g_kp  [NBH*SEQ*MMP];   // [bh][n][m]
__device__ float g_ks  [NBH*MMP];
__device__ float g_part[NBH*8*MMP];
__device__ float g_ctx [NBH*MMP*DH_];   // [bh][m][e], zero-padded m>=266
__device__ float g_att [ROWS*ID_];
__device__ float g_y   [ROWS*2048];
__device__ float g_glu [ROWS*INNER_];
__device__ float g_dw  [ROWS*INNER_];

// ======================================================================
// bf16-split (3-MMA) tensor-core GEMM, 2-stage smem pipelined.
// C = alpha*(A @ W^T) [+bias][+resid] ; optional permuted output for qp/kp.
// ======================================================================

__device__ __forceinline__ uint32_t pk2(__nv_bfloat16 a, __nv_bfloat16 b) {
    __nv_bfloat162 t = __halves2bfloat162(a, b);
    return *reinterpret_cast<uint32_t*>(&t);
}
__device__ __forceinline__ uint32_t pkf2(float a, float b) {
    __nv_bfloat162 t = __floats2bfloat162_rn(a, b);
    return *reinterpret_cast<uint32_t*>(&t);
}
__device__ __forceinline__ void ldm4(uint32_t* r, uint32_t addr) {
    asm volatile("ldmatrix.sync.aligned.m8n8.x4.shared.b16 {%0,%1,%2,%3}, [%4];\n"
                 : "=r"(r[0]), "=r"(r[1]), "=r"(r[2]), "=r"(r[3]) : "r"(addr));
}
__device__ __forceinline__ void mma_bf16(float* c, const uint32_t* a, const uint32_t* b) {
    asm volatile(
        "mma.sync.aligned.m16n8k16.row.col.f32.bf16.bf16.f32 "
        "{%0,%1,%2,%3}, {%4,%5,%6,%7}, {%8,%9}, {%0,%1,%2,%3};\n"
        : "+f"(c[0]), "+f"(c[1]), "+f"(c[2]), "+f"(c[3])
        : "r"(a[0]), "r"(a[1]), "r"(a[2]), "r"(a[3]), "r"(b[0]), "r"(b[1]));
}

#define ASTR 40                       // 80B rows: 16B-aligned, bank-clean
#define PLANE_ELEMS (128*ASTR)        // one plane (hi or lo)
#define PLANE_BYTES (PLANE_ELEMS*2)
#define STAGE_BYTES (2*PLANE_BYTES)   // hi+lo
#define MAT_ELEMS   (4*PLANE_ELEMS)   // 2 stages x 2 planes
#define GEMM_SMEM   (2*MAT_ELEMS*2)   // bytes total (A+B) = 81920

__global__ __launch_bounds__(256, 1)
void gemm_bf16x3(const float* __restrict__ A, const float* __restrict__ W,
                 float* __restrict__ C, const float* __restrict__ bias,
                 const float* __restrict__ resid,
                 int Mdim, int Ndim, int Kdim, float alpha, int permute)
{
    extern __shared__ __nv_bfloat16 dynsm[];
    __nv_bfloat16* Asm = dynsm;             // [stage][plane][128][ASTR]
    __nv_bfloat16* Bsm = dynsm + MAT_ELEMS;

    const int tid  = threadIdx.x;
    const int lane = tid & 31;
    const int warp = tid >> 5;
    const int wm = (warp & 1) * 64;
    const int wn = (warp >> 1) * 32;
    const int bm = blockIdx.y * 128;
    const int bn = blockIdx.x * 128;

    const int r0 = tid >> 3;           // row base (0..31), +u*32
    const int kk = (tid & 7) * 4;      // k offset within 32

    float4 pa[4], pb[4];

    float acc[4][4][4];
    #pragma unroll
    for (int i = 0; i < 4; i++)
        #pragma unroll
        for (int j = 0; j < 4; j++)
            #pragma unroll
            for (int t = 0; t < 4; t++) acc[i][j][t] = 0.f;

    const int a_m = lane & 15;
    const int a_k = (lane >> 4) << 3;
    const int b_n = (lane & 7) | ((lane & 16) >> 1);
    const int b_k = lane & 8;

    uint32_t sA = (uint32_t)__cvta_generic_to_shared(Asm);
    uint32_t sB = (uint32_t)__cvta_generic_to_shared(Bsm);

    const int KT = Kdim >> 5;

    // ---- helpers as lambdas ----
    auto loadg = [&](int kt) {
        #pragma unroll
        for (int u = 0; u < 4; u++)
            pa[u] = *(const float4*)&A[(size_t)(bm + r0 + u*32) * Kdim + kt*32 + kk];
        #pragma unroll
        for (int u = 0; u < 4; u++) {
            int wrow = bn + r0 + u*32;
            pb[u] = (wrow < Ndim) ? *(const float4*)&W[(size_t)wrow * Kdim + kt*32 + kk]
                                  : make_float4(0.f, 0.f, 0.f, 0.f);
        }
    };
    auto storestage = [&](int st) {
        #pragma unroll
        for (int u = 0; u < 4; u++) {
            int row = r0 + u*32;
            {
                float4 v = pa[u];
                __nv_bfloat16 h0 = __float2bfloat16(v.x), h1 = __float2bfloat16(v.y),
                              h2 = __float2bfloat16(v.z), h3 = __float2bfloat16(v.w);
                uint2 hi, lo;
                hi.x = pk2(h0, h1); hi.y = pk2(h2, h3);
                lo.x = pkf2(v.x - __bfloat162float(h0), v.y - __bfloat162float(h1));
                lo.y = pkf2(v.z - __bfloat162float(h2), v.w - __bfloat162float(h3));
                *(uint2*)&Asm[(st*2 + 0)*PLANE_ELEMS + row*ASTR + kk] = hi;
                *(uint2*)&Asm[(st*2 + 1)*PLANE_ELEMS + row*ASTR + kk] = lo;
            }
            {
                float4 v = pb[u];
                __nv_bfloat16 h0 = __float2bfloat16(v.x), h1 = __float2bfloat16(v.y),
                              h2 = __float2bfloat16(v.z), h3 = __float2bfloat16(v.w);
                uint2 hi, lo;
                hi.x = pk2(h0, h1); hi.y = pk2(h2, h3);
                lo.x = pkf2(v.x - __bfloat162float(h0), v.y - __bfloat162float(h1));
                lo.y = pkf2(v.z - __bfloat162float(h2), v.w - __bfloat162float(h3));
                *(uint2*)&Bsm[(st*2 + 0)*PLANE_ELEMS + row*ASTR + kk] = hi;
                *(uint2*)&Bsm[(st*2 + 1)*PLANE_ELEMS + row*ASTR + kk] = lo;
            }
        }
    };

    // prologue: fill stage 0, prefetch kt=1 into regs
    loadg(0);
    storestage(0);
    __syncthreads();
    if (KT > 1) loadg(1);

    int s = 0;
    for (int kt = 0; kt < KT; kt++) {
        if (kt + 1 < KT) storestage(s ^ 1);   // regs currently hold kt+1
        if (kt + 2 < KT) loadg(kt + 2);

        const uint32_t aBase = sA + (uint32_t)s * STAGE_BYTES;
        const uint32_t bBase = sB + (uint32_t)s * STAGE_BYTES;
        #pragma unroll
        for (int ks = 0; ks < 2; ks++) {
            uint32_t bh[4][2], bl[4][2];
            #pragma unroll
            for (int p = 0; p < 2; p++) {
                uint32_t addr = bBase + (uint32_t)(((wn + p*16 + b_n) * ASTR) + ks*16 + b_k) * 2;
                uint32_t r[4];
                ldm4(r, addr);
                bh[2*p][0] = r[0]; bh[2*p][1] = r[1];
                bh[2*p+1][0] = r[2]; bh[2*p+1][1] = r[3];
                ldm4(r, addr + PLANE_BYTES);
                bl[2*p][0] = r[0]; bl[2*p][1] = r[1];
                bl[2*p+1][0] = r[2]; bl[2*p+1][1] = r[3];
            }
            #pragma unroll
            for (int mt = 0; mt < 4; mt++) {
                uint32_t ah[4], al[4];
                uint32_t addr = aBase + (uint32_t)(((wm + mt*16 + a_m) * ASTR) + ks*16 + a_k) * 2;
                ldm4(ah, addr);
                ldm4(al, addr + PLANE_BYTES);
                #pragma unroll
                for (int nt = 0; nt < 4; nt++) {
                    mma_bf16(acc[mt][nt], ah, bh[nt]);
                    mma_bf16(acc[mt][nt], ah, bl[nt]);
                    mma_bf16(acc[mt][nt], al, bh[nt]);
                }
            }
        }
        __syncthreads();
        s ^= 1;
    }

    // epilogue
    const int gr = lane >> 2;
    const int gc = (lane & 3) * 2;
    #pragma unroll
    for (int mt = 0; mt < 4; mt++) {
        #pragma unroll
        for (int nt = 0; nt < 4; nt++) {
            const float* cp = acc[mt][nt];
            int row = bm + wm + mt*16 + gr;
            int col = bn + wn + nt*8 + gc;
            #pragma unroll
            for (int half = 0; half < 2; half++) {
                int rr = row + half*8;
                #pragma unroll
                for (int j = 0; j < 2; j++) {
                    int cc = col + j;
                    if (cc < Ndim) {
                        float val = cp[half*2 + j] * alpha;
                        if (bias)  val += bias[cc];
                        if (resid) val += resid[(size_t)rr * Ndim + cc];
                        if (permute) {
                            // rr = (b*SEQ+n)*H + h  ->  [bh][n][m] stride MMP
                            int hh = rr & 7;
                            int bn2 = rr >> 3;
                            int bb = bn2 >> 11;
                            int nn = bn2 & 2047;
                            C[((size_t)(bb*8 + hh) * SEQ + nn) * MMP + cc] = val;
                        } else {
                            C[(size_t)rr * Ndim + cc] = val;
                        }
                    }
                }
            }
        }
    }
}

// ---------------- LayerNorm over D=512, one block per row -----------------
__global__ void ln_kernel(const float* __restrict__ x, const float* __restrict__ g,
                          const float* __restrict__ b, float* __restrict__ out)
{
    const int r = blockIdx.x;
    const int t = threadIdx.x;   // 128 threads, float4 each -> 512
    const float4 v = ((const float4*)(x + (size_t)r * D_))[t];
    float s  = v.x + v.y + v.z + v.w;
    float ss = v.x*v.x + v.y*v.y + v.z*v.z + v.w*v.w;
    __shared__ float rs[128], rss[128];
    rs[t] = s; rss[t] = ss;
    __syncthreads();
    for (int o = 64; o > 0; o >>= 1) {
        if (t < o) { rs[t] += rs[t+o]; rss[t] += rss[t+o]; }
        __syncthreads();
    }
    const float mu   = rs[0] * (1.f / D_);
    const float var  = rss[0] * (1.f / D_) - mu * mu;
    const float rstd = rsqrtf(var + 1e-5f);
    const float4 gg = ((const float4*)g)[t];
    const float4 bb = ((const float4*)b)[t];
    float4 o4;
    o4.x = (v.x - mu) * rstd * gg.x + bb.x;
    o4.y = (v.y - mu) * rstd * gg.y + bb.y;
    o4.z = (v.z - mu) * rstd * gg.z + bb.z;
    o4.w = (v.w - mu) * rstd * gg.w + bb.w;
    ((float4*)(out + (size_t)r * D_))[t] = o4;
}

// ---------------- FAVOR postprocess: warp per row ([bh][n][m] layout) ------
__global__ __launch_bounds__(256)
void favor_post2(float* __restrict__ fp, const float* __restrict__ data,
                 int isQuery, float ratio)
{
    const int lane = threadIdx.x & 31;
    const int w    = threadIdx.x >> 5;
    const int bh   = blockIdx.y;
    const int n    = blockIdx.x * 8 + w;
    const int b = bh >> 3, h = bh & 7;

    float* prow = fp + ((size_t)bh * SEQ + n) * MMP;
    const float* drow = data + ((size_t)((b * SEQ + n) * H_) + h) * DH_;

    float2 d2 = ((const float2*)drow)[lane];
    float s = d2.x*d2.x + d2.y*d2.y;
    #pragma unroll
    for (int o = 16; o > 0; o >>= 1) s += __shfl_xor_sync(0xffffffffu, s, o);
    const float diag = s * 0.0625f;   // 0.5*dn^2

    if (isQuery) {
        float mx = -1e30f;
        #pragma unroll
        for (int j = 0; j < 9; j++) {
            int m = j*32 + lane;
            if (m < MM) mx = fmaxf(mx, prow[m]);
        }
        #pragma unroll
        for (int o = 16; o > 0; o >>= 1) mx = fmaxf(mx, __shfl_xor_sync(0xffffffffu, mx, o));
        #pragma unroll
        for (int j = 0; j < 9; j++) {
            int m = j*32 + lane;
            if (m < MM)       prow[m] = ratio * (expf(prow[m] - diag - mx) + 1e-4f);
            else if (m < MMP) prow[m] = 0.f;
        }
    } else {
        #pragma unroll
        for (int j = 0; j < 9; j++) {
            int m = j*32 + lane;
            if (m < MM)       prow[m] = ratio * expf(prow[m] - diag + 1e-4f);
            else if (m < MMP) prow[m] = 0.f;
        }
    }
}

// ---------------- ksum two-stage (coalesced over [bh][n][m]) ---------------
__global__ void ksum1(const float* __restrict__ kp, float* __restrict__ part)
{
    const int bh = blockIdx.y;
    const int chunk = blockIdx.x;     // 0..7
    const int m = threadIdx.x;        // 288 threads, guard m<MMP
    if (m >= MMP) return;
    const float* base = kp + ((size_t)bh * SEQ + chunk * 256) * MMP + m;
    float s0 = 0.f, s1 = 0.f, s2 = 0.f, s3 = 0.f;
    for (int n = 0; n < 256; n += 4) {
        s0 += base[(size_t)(n+0) * MMP];
        s1 += base[(size_t)(n+1) * MMP];
        s2 += base[(size_t)(n+2) * MMP];
        s3 += base[(size_t)(n+3) * MMP];
    }
    part[((size_t)bh * 8 + chunk) * MMP + m] = (s0 + s1) + (s2 + s3);
}
__global__ void ksum2(const float* __restrict__ part, float* __restrict__ ks)
{
    const int bh = blockIdx.x;
    const int m = threadIdx.x;
    if (m >= MMP) return;
    float s = 0.f;
    #pragma unroll
    for (int c = 0; c < 8; c++) s += part[((size_t)bh * 8 + c) * MMP + m];
    ks[(size_t)bh * MMP + m] = s;
}

// ---------------- context: ctx[bh] (MMPx64) = kp[bh]^T @ v[bh] --------------
__global__ __launch_bounds__(256)
void ctx_kernel(const float* __restrict__ kp, const float* __restrict__ v,
                float* __restrict__ ctx)
{
    const int bh = blockIdx.y;
    const int b = bh >> 3, h = bh & 7;
    const int m0 = blockIdx.x * 64;
    const float* kpb = kp + (size_t)bh * SEQ * MMP;
    const float* vb  = v + ((size_t)b * SEQ * H_ + h) * DH_;

    __shared__ float As[32][65];  // [n][m]
    __shared__ float Bs[32][65];  // [n][e]
    const int tx = threadIdx.x & 15, ty = threadIdx.x >> 4;

    float acc[4][4];
    #pragma unroll
    for (int i = 0; i < 4; i++)
        #pragma unroll
        for (int j = 0; j < 4; j++) acc[i][j] = 0.f;

    for (int n0 = 0; n0 < SEQ; n0 += 32) {
        #pragma unroll
        for (int u = 0; u < 8; u++) {
            int f = threadIdx.x + u*256;
            int nn = f >> 6, mm = f & 63;
            int gm = m0 + mm;
            As[nn][mm] = (gm < MMP) ? kpb[(size_t)(n0 + nn) * MMP + gm] : 0.f;
            Bs[nn][mm] = vb[(size_t)(n0 + nn) * (H_*DH_) + mm];
        }
        __syncthreads();
        #pragma unroll
        for (int kk2 = 0; kk2 < 32; kk2++) {
            float a[4], bb[4];
            #pragma unroll
            for (int i = 0; i < 4; i++) a[i] = As[kk2][ty*4 + i];
            #pragma unroll
            for (int j = 0; j < 4; j++) bb[j] = Bs[kk2][tx*4 + j];
            #pragma unroll
            for (int i = 0; i < 4; i++)
                #pragma unroll
                for (int j = 0; j < 4; j++) acc[i][j] += a[i] * bb[j];
        }
        __syncthreads();
    }

    float* cb = ctx + (size_t)bh * MMP * DH_;
    #pragma unroll
    for (int i = 0; i < 4; i++) {
        int m = m0 + ty*4 + i;
        if (m < MMP) {
            #pragma unroll
            for (int j = 0; j < 4; j++)
                cb[(size_t)m * DH_ + tx*4 + j] = acc[i][j];
        }
    }
}

// ---------------- attention out, smem-tiled with ctx reuse ------------------
__global__ __launch_bounds__(256)
void attn_out2(const float* __restrict__ qp, const float* __restrict__ ks,
               const float* __restrict__ ctx, float* __restrict__ out)
{
    const int bh = blockIdx.y;
    const int b = bh >> 3, h = bh & 7;
    const int n0 = blockIdx.x * 32;
    const int t = threadIdx.x;
    const int ri = t >> 3;
    const int e0 = (t & 7) * 8;

    __shared__ __align__(16) float cs[64][68];
    __shared__ __align__(16) float qs[32][68];
    __shared__ float dsum[32];

    if (t < 32) dsum[t] = 0.f;
    float acc[8];
    #pragma unroll
    for (int j = 0; j < 8; j++) acc[j] = 0.f;

    const float* ksb = ks + (size_t)bh * MMP;
    const float* qpb = qp + ((size_t)bh * SEQ + n0) * MMP;
    const float4 z4 = make_float4(0.f, 0.f, 0.f, 0.f);

    for (int m0 = 0; m0 < MMP; m0 += 64) {
        // ctx chunk: 64x64 floats
        #pragma unroll
        for (int u = 0; u < 4; u++) {
            int f = t + u*256;
            int mm = f >> 4;
            int ee = (f & 15) * 4;
            int gm = m0 + mm;
            float4 v = (gm < MMP) ? *(const float4*)&ctx[((size_t)bh * MMP + gm) * DH_ + ee] : z4;
            *(float4*)&cs[mm][ee] = v;
        }
        // qp chunk: 32 rows x 64 m (float4)
        #pragma unroll
        for (int u = 0; u < 2; u++) {
            int f = t + u*256;          // float4 slots: 32*16
            int rr = f >> 4;
            int m4 = (f & 15) * 4;
            int gm = m0 + m4;
            float4 v = (gm < MMP) ? *(const float4*)&qpb[(size_t)rr * MMP + gm] : z4;
            *(float4*)&qs[rr][m4] = v;
        }
        __syncthreads();

        if (t < 32) {
            const int lim = (MMP - m0 < 64) ? (MMP - m0) : 64;
            float s = 0.f;
            for (int mm = 0; mm < lim; mm++) s += qs[t][mm] * ksb[m0 + mm];
            dsum[t] += s;
        }

        #pragma unroll 4
        for (int mm = 0; mm < 64; mm++) {
            float qv = qs[ri][mm];
            float4 c0 = *(const float4*)&cs[mm][e0];
            float4 c1 = *(const float4*)&cs[mm][e0 + 4];
            acc[0] += qv * c0.x; acc[1] += qv * c0.y;
            acc[2] += qv * c0.z; acc[3] += qv * c0.w;
            acc[4] += qv * c1.x; acc[5] += qv * c1.y;
            acc[6] += qv * c1.z; acc[7] += qv * c1.w;
        }
        __syncthreads();
    }

    const float dinv = 1.f / (dsum[ri] + 1e-8f);
    float* orow = out + ((size_t)(b * SEQ + n0 + ri) * H_ + h) * DH_ + e0;
    float4 o0 = make_float4(acc[0]*dinv, acc[1]*dinv, acc[2]*dinv, acc[3]*dinv);
    float4 o1 = make_float4(acc[4]*dinv, acc[5]*dinv, acc[6]*dinv, acc[7]*dinv);
    *(float4*)&orow[0] = o0;
    *(float4*)&orow[4] = o1;
}

// ---------------- GLU: a * sigmoid(g), float4 -------------------------------
__global__ void glu_kernel(const float* __restrict__ y, float* __restrict__ out)
{
    size_t idx = (size_t)blockIdx.x * 256 + threadIdx.x;  // float4 index, ROWS*INNER/4
    size_t row = idx >> 8;            // 256 float4 per row of INNER
    int c4 = (int)(idx & 255);
    const float4 a = ((const float4*)y)[row * 512 + c4];
    const float4 g = ((const float4*)y)[row * 512 + 256 + c4];
    float4 o;
    o.x = a.x / (1.f + expf(-g.x));
    o.y = a.y / (1.f + expf(-g.y));
    o.z = a.z / (1.f + expf(-g.z));
    o.w = a.w / (1.f + expf(-g.w));
    ((float4*)out)[idx] = o;
}

// ---------------- depthwise conv (K=31, pad 15) + SiLU, tiled ---------------
#define DC_CH 128
#define DC_TN 32
__global__ __launch_bounds__(256)
void dwconv2(const float* __restrict__ gin, const float* __restrict__ w,
             const float* __restrict__ bias, float* __restrict__ out)
{
    __shared__ float sin_[DC_TN + 30][DC_CH];
    __shared__ float sw[DC_CH * KW];

    const int c0 = blockIdx.x * DC_CH;
    const int n0 = blockIdx.y * DC_TN;
    const int b  = blockIdx.z;
    const int t  = threadIdx.x;

    // weights: 128*31 consecutive floats
    for (int i = t; i < DC_CH * KW; i += 256)
        sw[i] = w[(size_t)c0 * KW + i];
    // input tile: rows n0-15 .. n0+DC_TN+14
    #pragma unroll
    for (int u = 0; u < (DC_TN + 30) * DC_CH / 256; u++) {
        int f = t + u * 256;
        int rowi = f >> 7;        // 0..61
        int ch = f & 127;
        int n = n0 + rowi - 15;
        sin_[rowi][ch] = ((unsigned)n < SEQ)
            ? gin[((size_t)(b * SEQ + n) << 10) + c0 + ch] : 0.f;
    }
    __syncthreads();

    const int ch = t & 127;
    const int nl0 = (t >> 7) * 16;   // 0 or 16

    float wr[KW];
    #pragma unroll
    for (int k = 0; k < KW; k++) wr[k] = sw[ch * KW + k];
    const float bb = bias[c0 + ch];

    #pragma unroll
    for (int i = 0; i < 16; i++) {
        float acc = bb;
        #pragma unroll
        for (int k = 0; k < KW; k++)
            acc += sin_[nl0 + i + k][ch] * wr[k];
        float o = acc / (1.f + expf(-acc));
        out[((size_t)(b * SEQ + n0 + nl0 + i) << 10) + c0 + ch] = o;
    }
}

// ---------------- host orchestration ----------------------------------------
static inline void run_gemm(const float* A, const float* W, float* C,
                            const float* bias, const float* resid,
                            int Mdim, int Ndim, int Kdim, float alpha, int permute)
{
    dim3 grid((Ndim + 127) / 128, Mdim / 128);
    gemm_bf16x3<<<grid, 256, GEMM_SMEM>>>(A, W, C, bias, resid, Mdim, Ndim, Kdim, alpha, permute);
}

extern "C" void kernel_launch(void* const* d_in, const int* in_sizes, int n_in,
                              void* d_out, int out_size)
{
    const float* x    = (const float*)d_in[0];
    const float* ln1g = (const float*)d_in[1];
    const float* ln1b = (const float*)d_in[2];
    const float* wq   = (const float*)d_in[3];
    const float* bq   = (const float*)d_in[4];
    const float* wk   = (const float*)d_in[5];
    const float* bk   = (const float*)d_in[6];
    const float* wv   = (const float*)d_in[7];
    const float* bv   = (const float*)d_in[8];
    const float* wo   = (const float*)d_in[9];
    const float* bo   = (const float*)d_in[10];
    const float* proj = (const float*)d_in[11];
    const float* ln2g = (const float*)d_in[12];
    const float* ln2b = (const float*)d_in[13];
    const float* pw1w = (const float*)d_in[14];
    const float* pw1b = (const float*)d_in[15];
    const float* dww  = (const float*)d_in[16];
    const float* dwb  = (const float*)d_in[17];
    const float* pw2w = (const float*)d_in[18];
    const float* pw2b = (const float*)d_in[19];
    float* xo = (float*)d_out;

    static int smem_set = 0;
    if (!smem_set) {
        cudaFuncSetAttribute(gemm_bf16x3, cudaFuncAttributeMaxDynamicSharedMemorySize, GEMM_SMEM);
        smem_set = 1;
    }

    float *h, *q, *k, *v, *qp, *kp, *ks, *part, *ctx, *att, *y, *glu, *dw;
    cudaGetSymbolAddress((void**)&h,    g_h);
    cudaGetSymbolAddress((void**)&q,    g_q);
    cudaGetSymbolAddress((void**)&k,    g_k);
    cudaGetSymbolAddress((void**)&v,    g_v);
    cudaGetSymbolAddress((void**)&qp,   g_qp);
    cudaGetSymbolAddress((void**)&kp,   g_kp);
    cudaGetSymbolAddress((void**)&ks,   g_ks);
    cudaGetSymbolAddress((void**)&part, g_part);
    cudaGetSymbolAddress((void**)&ctx,  g_ctx);
    cudaGetSymbolAddress((void**)&att,  g_att);
    cudaGetSymbolAddress((void**)&y,    g_y);
    cudaGetSymbolAddress((void**)&glu,  g_glu);
    cudaGetSymbolAddress((void**)&dw,   g_dw);

    cudaMemcpyAsync(xo, x, (size_t)ROWS * D_ * sizeof(float),
                    cudaMemcpyDeviceToDevice);

    const float dn    = (float)(1.0 / sqrt(sqrt(64.0)));   // 64^-0.25
    const float ratio = (float)(1.0 / sqrt(266.0));        // M^-0.5

    for (int l = 0; l < LNUM; l++) {
        // LN1
        ln_kernel<<<ROWS, 128>>>(xo, ln1g + (size_t)l*D_, ln1b + (size_t)l*D_, h);
        // QKV
        run_gemm(h, wq + (size_t)l*ID_*D_, q, bq + (size_t)l*ID_, nullptr, ROWS, ID_, D_, 1.f, 0);
        run_gemm(h, wk + (size_t)l*ID_*D_, k, bk + (size_t)l*ID_, nullptr, ROWS, ID_, D_, 1.f, 0);
        run_gemm(h, wv + (size_t)l*ID_*D_, v, bv + (size_t)l*ID_, nullptr, ROWS, ID_, D_, 1.f, 0);
        // FAVOR feature maps (permuted [bh][n][m] output), then exp postprocess
        run_gemm(q, proj + (size_t)l*MM*DH_, qp, nullptr, nullptr, RH, MM, DH_, dn, 1);
        run_gemm(k, proj + (size_t)l*MM*DH_, kp, nullptr, nullptr, RH, MM, DH_, dn, 1);
        {
            dim3 fg(SEQ / 8, NBH);
            favor_post2<<<fg, 256>>>(qp, q, 1, ratio);
            favor_post2<<<fg, 256>>>(kp, k, 0, ratio);
        }
        // linear attention
        {
            dim3 k1(8, NBH);
            ksum1<<<k1, 288>>>(kp, part);
            ksum2<<<NBH, 288>>>(part, ks);
            dim3 cg((MMP + 63) / 64, NBH);
            ctx_kernel<<<cg, 256>>>(kp, v, ctx);
            dim3 ag(SEQ / 32, NBH);
            attn_out2<<<ag, 256>>>(qp, ks, ctx, att);
        }
        // output projection + residual (in-place on xo)
        run_gemm(att, wo + (size_t)l*ID_*D_, xo, bo + (size_t)l*D_, xo, ROWS, D_, ID_, 1.f, 0);
        // LN2 + conv-FFN
        ln_kernel<<<ROWS, 128>>>(xo, ln2g + (size_t)l*D_, ln2b + (size_t)l*D_, h);
        run_gemm(h, pw1w + (size_t)l*2048*D_, y, pw1b + (size_t)l*2048, nullptr, ROWS, 2048, D_, 1.f, 0);
        glu_kernel<<<(ROWS*INNER_)/(256*4), 256>>>(y, glu);
        {
            dim3 dg(INNER_/DC_CH, SEQ/DC_TN, B_);
            dwconv2<<<dg, 256>>>(glu, dww + (size_t)l*INNER_*KW, dwb + (size_t)l*INNER_, dw);
        }
        run_gemm(dw, pw2w + (size_t)l*D_*INNER_, xo, pw2b + (size_t)l*D_, xo, ROWS, D_, INNER_, 1.f, 0);
    }
}

// round 5
// speedup vs baseline: 2.0930x; 1.0692x over previous
#include <cuda_runtime.h>
#include <cuda_bf16.h>
#include <math.h>
#include <stdint.h>

// ---------------- problem constants ----------------
#define B_     4
#define SEQ    2048
#define D_     512
#define H_     8
#define DH_    64
#define ID_    512
#define MM     266
#define MMP    272          // padded feature dim (16B-aligned rows)
#define INNER_ 1024
#define KW     31
#define LNUM   6
#define ROWS   (B_*SEQ)     // 8192 token rows
#define RH     (ROWS*H_)    // 65536 (b,n,h) rows
#define NBH    (B_*H_)      // 32

// ---------------- device scratch (no allocations allowed) ----------------
__device__ float g_h   [ROWS*D_];
__device__ float g_q   [ROWS*ID_];
__device__ float g_k   [ROWS*ID_];
__device__ float g_v   [ROWS*ID_];
__device__ float g_qp  [NBH*SEQ*MMP];   // [bh][n][m]
__device__ float g_kp  [NBH*SEQ*MMP];   // [bh][n][m]
__device__ float g_ks  [NBH*MMP];
__device__ float g_part[NBH*8*MMP];
__device__ float g_ctx [NBH*MMP*DH_];   // [bh][m][e], zero-padded m>=266
__device__ float g_att [ROWS*ID_];
__device__ float g_y   [ROWS*2048];
__device__ float g_glu [ROWS*INNER_];
__device__ float g_dw  [ROWS*INNER_];

// ======================================================================
// bf16-split (3-MMA) tensor-core GEMM, single-stage smem, 2 CTAs/SM.
// C = alpha*(A @ W^T) [+bias][+resid] ; optional permuted output for qp/kp.
// ======================================================================

__device__ __forceinline__ uint32_t pk2(__nv_bfloat16 a, __nv_bfloat16 b) {
    __nv_bfloat162 t = __halves2bfloat162(a, b);
    return *reinterpret_cast<uint32_t*>(&t);
}
__device__ __forceinline__ uint32_t pkf2(float a, float b) {
    __nv_bfloat162 t = __floats2bfloat162_rn(a, b);
    return *reinterpret_cast<uint32_t*>(&t);
}
__device__ __forceinline__ void ldm4(uint32_t* r, uint32_t addr) {
    asm volatile("ldmatrix.sync.aligned.m8n8.x4.shared.b16 {%0,%1,%2,%3}, [%4];\n"
                 : "=r"(r[0]), "=r"(r[1]), "=r"(r[2]), "=r"(r[3]) : "r"(addr));
}
__device__ __forceinline__ void mma_bf16(float* c, const uint32_t* a, const uint32_t* b) {
    asm volatile(
        "mma.sync.aligned.m16n8k16.row.col.f32.bf16.bf16.f32 "
        "{%0,%1,%2,%3}, {%4,%5,%6,%7}, {%8,%9}, {%0,%1,%2,%3};\n"
        : "+f"(c[0]), "+f"(c[1]), "+f"(c[2]), "+f"(c[3])
        : "r"(a[0]), "r"(a[1]), "r"(a[2]), "r"(a[3]), "r"(b[0]), "r"(b[1]));
}

#define ASTR 40                       // 80B rows: 16B-aligned, bank-clean
#define PLANE_ELEMS (128*ASTR)        // one plane (hi or lo)
#define PLANE_BYTES (PLANE_ELEMS*2)

__global__ __launch_bounds__(256, 2)
void gemm_bf16x3(const float* __restrict__ A, const float* __restrict__ W,
                 float* __restrict__ C, const float* __restrict__ bias,
                 const float* __restrict__ resid,
                 int Mdim, int Ndim, int Kdim, float alpha, int permute)
{
    __shared__ __align__(16) __nv_bfloat16 Asm[2][128][ASTR];   // [plane][row][k]
    __shared__ __align__(16) __nv_bfloat16 Bsm[2][128][ASTR];

    const int tid  = threadIdx.x;
    const int lane = tid & 31;
    const int warp = tid >> 5;
    const int wm = (warp & 1) * 64;
    const int wn = (warp >> 1) * 32;
    const int bm = blockIdx.y * 128;
    const int bn = blockIdx.x * 128;

    const int r0 = tid >> 3;           // row base (0..31), +u*32
    const int kk = (tid & 7) * 4;      // k offset within 32

    float acc[4][4][4];
    #pragma unroll
    for (int i = 0; i < 4; i++)
        #pragma unroll
        for (int j = 0; j < 4; j++)
            #pragma unroll
            for (int t = 0; t < 4; t++) acc[i][j][t] = 0.f;

    const int a_m = lane & 15;
    const int a_k = (lane >> 4) << 3;
    const int b_n = (lane & 7) | ((lane & 16) >> 1);
    const int b_k = lane & 8;

    const uint32_t sA = (uint32_t)__cvta_generic_to_shared(&Asm[0][0][0]);
    const uint32_t sB = (uint32_t)__cvta_generic_to_shared(&Bsm[0][0][0]);

    const int KT = Kdim >> 5;

    for (int kt = 0; kt < KT; kt++) {
        // load + convert + store (hi and lo planes)
        #pragma unroll
        for (int u = 0; u < 4; u++) {
            const int row = r0 + u*32;
            {
                float4 v = *(const float4*)&A[(size_t)(bm + row) * Kdim + kt*32 + kk];
                __nv_bfloat16 h0 = __float2bfloat16(v.x), h1 = __float2bfloat16(v.y),
                              h2 = __float2bfloat16(v.z), h3 = __float2bfloat16(v.w);
                uint2 hi, lo;
                hi.x = pk2(h0, h1); hi.y = pk2(h2, h3);
                lo.x = pkf2(v.x - __bfloat162float(h0), v.y - __bfloat162float(h1));
                lo.y = pkf2(v.z - __bfloat162float(h2), v.w - __bfloat162float(h3));
                *(uint2*)&Asm[0][row][kk] = hi;
                *(uint2*)&Asm[1][row][kk] = lo;
            }
            {
                const int wrow = bn + row;
                float4 v = (wrow < Ndim) ? *(const float4*)&W[(size_t)wrow * Kdim + kt*32 + kk]
                                         : make_float4(0.f, 0.f, 0.f, 0.f);
                __nv_bfloat16 h0 = __float2bfloat16(v.x), h1 = __float2bfloat16(v.y),
                              h2 = __float2bfloat16(v.z), h3 = __float2bfloat16(v.w);
                uint2 hi, lo;
                hi.x = pk2(h0, h1); hi.y = pk2(h2, h3);
                lo.x = pkf2(v.x - __bfloat162float(h0), v.y - __bfloat162float(h1));
                lo.y = pkf2(v.z - __bfloat162float(h2), v.w - __bfloat162float(h3));
                *(uint2*)&Bsm[0][row][kk] = hi;
                *(uint2*)&Bsm[1][row][kk] = lo;
            }
        }
        __syncthreads();

        #pragma unroll
        for (int ks = 0; ks < 2; ks++) {
            uint32_t bh[4][2], bl[4][2];
            #pragma unroll
            for (int p = 0; p < 2; p++) {
                uint32_t addr = sB + (uint32_t)(((wn + p*16 + b_n) * ASTR) + ks*16 + b_k) * 2;
                uint32_t r[4];
                ldm4(r, addr);
                bh[2*p][0] = r[0]; bh[2*p][1] = r[1];
                bh[2*p+1][0] = r[2]; bh[2*p+1][1] = r[3];
                ldm4(r, addr + PLANE_BYTES);
                bl[2*p][0] = r[0]; bl[2*p][1] = r[1];
                bl[2*p+1][0] = r[2]; bl[2*p+1][1] = r[3];
            }
            #pragma unroll
            for (int mt = 0; mt < 4; mt++) {
                uint32_t ah[4], al[4];
                uint32_t addr = sA + (uint32_t)(((wm + mt*16 + a_m) * ASTR) + ks*16 + a_k) * 2;
                ldm4(ah, addr);
                ldm4(al, addr + PLANE_BYTES);
                #pragma unroll
                for (int nt = 0; nt < 4; nt++) {
                    mma_bf16(acc[mt][nt], ah, bh[nt]);
                    mma_bf16(acc[mt][nt], ah, bl[nt]);
                    mma_bf16(acc[mt][nt], al, bh[nt]);
                }
            }
        }
        __syncthreads();
    }

    // epilogue
    const int gr = lane >> 2;
    const int gc = (lane & 3) * 2;
    #pragma unroll
    for (int mt = 0; mt < 4; mt++) {
        #pragma unroll
        for (int nt = 0; nt < 4; nt++) {
            const float* cp = acc[mt][nt];
            int row = bm + wm + mt*16 + gr;
            int col = bn + wn + nt*8 + gc;
            #pragma unroll
            for (int half = 0; half < 2; half++) {
                int rr = row + half*8;
                #pragma unroll
                for (int j = 0; j < 2; j++) {
                    int cc = col + j;
                    if (cc < Ndim) {
                        float val = cp[half*2 + j] * alpha;
                        if (bias)  val += bias[cc];
                        if (resid) val += resid[(size_t)rr * Ndim + cc];
                        if (permute) {
                            // rr = (b*SEQ+n)*H + h  ->  [bh][n][m] stride MMP
                            int hh = rr & 7;
                            int bn2 = rr >> 3;
                            int bb = bn2 >> 11;
                            int nn = bn2 & 2047;
                            C[((size_t)(bb*8 + hh) * SEQ + nn) * MMP + cc] = val;
                        } else {
                            C[(size_t)rr * Ndim + cc] = val;
                        }
                    }
                }
            }
        }
    }
}

// ---------------- LayerNorm over D=512, one block per row -----------------
__global__ void ln_kernel(const float* __restrict__ x, const float* __restrict__ g,
                          const float* __restrict__ b, float* __restrict__ out)
{
    const int r = blockIdx.x;
    const int t = threadIdx.x;   // 128 threads, float4 each -> 512
    const float4 v = ((const float4*)(x + (size_t)r * D_))[t];
    float s  = v.x + v.y + v.z + v.w;
    float ss = v.x*v.x + v.y*v.y + v.z*v.z + v.w*v.w;
    __shared__ float rs[128], rss[128];
    rs[t] = s; rss[t] = ss;
    __syncthreads();
    for (int o = 64; o > 0; o >>= 1) {
        if (t < o) { rs[t] += rs[t+o]; rss[t] += rss[t+o]; }
        __syncthreads();
    }
    const float mu   = rs[0] * (1.f / D_);
    const float var  = rss[0] * (1.f / D_) - mu * mu;
    const float rstd = rsqrtf(var + 1e-5f);
    const float4 gg = ((const float4*)g)[t];
    const float4 bb = ((const float4*)b)[t];
    float4 o4;
    o4.x = (v.x - mu) * rstd * gg.x + bb.x;
    o4.y = (v.y - mu) * rstd * gg.y + bb.y;
    o4.z = (v.z - mu) * rstd * gg.z + bb.z;
    o4.w = (v.w - mu) * rstd * gg.w + bb.w;
    ((float4*)(out + (size_t)r * D_))[t] = o4;
}

// ---------------- FAVOR postprocess: warp per row ([bh][n][m] layout) ------
__global__ __launch_bounds__(256)
void favor_post2(float* __restrict__ fp, const float* __restrict__ data,
                 int isQuery, float ratio)
{
    const int lane = threadIdx.x & 31;
    const int w    = threadIdx.x >> 5;
    const int bh   = blockIdx.y;
    const int n    = blockIdx.x * 8 + w;
    const int b = bh >> 3, h = bh & 7;

    float* prow = fp + ((size_t)bh * SEQ + n) * MMP;
    const float* drow = data + ((size_t)((b * SEQ + n) * H_) + h) * DH_;

    float2 d2 = ((const float2*)drow)[lane];
    float s = d2.x*d2.x + d2.y*d2.y;
    #pragma unroll
    for (int o = 16; o > 0; o >>= 1) s += __shfl_xor_sync(0xffffffffu, s, o);
    const float diag = s * 0.0625f;   // 0.5*dn^2

    if (isQuery) {
        float mx = -1e30f;
        #pragma unroll
        for (int j = 0; j < 9; j++) {
            int m = j*32 + lane;
            if (m < MM) mx = fmaxf(mx, prow[m]);
        }
        #pragma unroll
        for (int o = 16; o > 0; o >>= 1) mx = fmaxf(mx, __shfl_xor_sync(0xffffffffu, mx, o));
        #pragma unroll
        for (int j = 0; j < 9; j++) {
            int m = j*32 + lane;
            if (m < MM)       prow[m] = ratio * (expf(prow[m] - diag - mx) + 1e-4f);
            else if (m < MMP) prow[m] = 0.f;
        }
    } else {
        #pragma unroll
        for (int j = 0; j < 9; j++) {
            int m = j*32 + lane;
            if (m < MM)       prow[m] = ratio * expf(prow[m] - diag + 1e-4f);
            else if (m < MMP) prow[m] = 0.f;
        }
    }
}

// ---------------- ksum two-stage (coalesced over [bh][n][m]) ---------------
__global__ void ksum1(const float* __restrict__ kp, float* __restrict__ part)
{
    const int bh = blockIdx.y;
    const int chunk = blockIdx.x;     // 0..7
    const int m = threadIdx.x;        // 288 threads, guard m<MMP
    if (m >= MMP) return;
    const float* base = kp + ((size_t)bh * SEQ + chunk * 256) * MMP + m;
    float s0 = 0.f, s1 = 0.f, s2 = 0.f, s3 = 0.f;
    for (int n = 0; n < 256; n += 4) {
        s0 += base[(size_t)(n+0) * MMP];
        s1 += base[(size_t)(n+1) * MMP];
        s2 += base[(size_t)(n+2) * MMP];
        s3 += base[(size_t)(n+3) * MMP];
    }
    part[((size_t)bh * 8 + chunk) * MMP + m] = (s0 + s1) + (s2 + s3);
}
__global__ void ksum2(const float* __restrict__ part, float* __restrict__ ks)
{
    const int bh = blockIdx.x;
    const int m = threadIdx.x;
    if (m >= MMP) return;
    float s = 0.f;
    #pragma unroll
    for (int c = 0; c < 8; c++) s += part[((size_t)bh * 8 + c) * MMP + m];
    ks[(size_t)bh * MMP + m] = s;
}

// ---------------- context: ctx[bh] (MMPx64) = kp[bh]^T @ v[bh] --------------
__global__ __launch_bounds__(256)
void ctx_kernel(const float* __restrict__ kp, const float* __restrict__ v,
                float* __restrict__ ctx)
{
    const int bh = blockIdx.y;
    const int b = bh >> 3, h = bh & 7;
    const int m0 = blockIdx.x * 64;
    const float* kpb = kp + (size_t)bh * SEQ * MMP;
    const float* vb  = v + ((size_t)b * SEQ * H_ + h) * DH_;

    __shared__ float As[32][65];  // [n][m]
    __shared__ float Bs[32][65];  // [n][e]
    const int tx = threadIdx.x & 15, ty = threadIdx.x >> 4;

    float acc[4][4];
    #pragma unroll
    for (int i = 0; i < 4; i++)
        #pragma unroll
        for (int j = 0; j < 4; j++) acc[i][j] = 0.f;

    for (int n0 = 0; n0 < SEQ; n0 += 32) {
        #pragma unroll
        for (int u = 0; u < 8; u++) {
            int f = threadIdx.x + u*256;
            int nn = f >> 6, mm = f & 63;
            int gm = m0 + mm;
            As[nn][mm] = (gm < MMP) ? kpb[(size_t)(n0 + nn) * MMP + gm] : 0.f;
            Bs[nn][mm] = vb[(size_t)(n0 + nn) * (H_*DH_) + mm];
        }
        __syncthreads();
        #pragma unroll
        for (int kk2 = 0; kk2 < 32; kk2++) {
            float a[4], bb[4];
            #pragma unroll
            for (int i = 0; i < 4; i++) a[i] = As[kk2][ty*4 + i];
            #pragma unroll
            for (int j = 0; j < 4; j++) bb[j] = Bs[kk2][tx*4 + j];
            #pragma unroll
            for (int i = 0; i < 4; i++)
                #pragma unroll
                for (int j = 0; j < 4; j++) acc[i][j] += a[i] * bb[j];
        }
        __syncthreads();
    }

    float* cb = ctx + (size_t)bh * MMP * DH_;
    #pragma unroll
    for (int i = 0; i < 4; i++) {
        int m = m0 + ty*4 + i;
        if (m < MMP) {
            #pragma unroll
            for (int j = 0; j < 4; j++)
                cb[(size_t)m * DH_ + tx*4 + j] = acc[i][j];
        }
    }
}

// ---------------- attention out, smem-tiled with ctx reuse ------------------
__global__ __launch_bounds__(256)
void attn_out2(const float* __restrict__ qp, const float* __restrict__ ks,
               const float* __restrict__ ctx, float* __restrict__ out)
{
    const int bh = blockIdx.y;
    const int b = bh >> 3, h = bh & 7;
    const int n0 = blockIdx.x * 32;
    const int t = threadIdx.x;
    const int ri = t >> 3;
    const int e0 = (t & 7) * 8;

    __shared__ __align__(16) float cs[64][68];
    __shared__ __align__(16) float qs[32][68];
    __shared__ float dsum[32];

    if (t < 32) dsum[t] = 0.f;
    float acc[8];
    #pragma unroll
    for (int j = 0; j < 8; j++) acc[j] = 0.f;

    const float* ksb = ks + (size_t)bh * MMP;
    const float* qpb = qp + ((size_t)bh * SEQ + n0) * MMP;
    const float4 z4 = make_float4(0.f, 0.f, 0.f, 0.f);

    for (int m0 = 0; m0 < MMP; m0 += 64) {
        // ctx chunk: 64x64 floats
        #pragma unroll
        for (int u = 0; u < 4; u++) {
            int f = t + u*256;
            int mm = f >> 4;
            int ee = (f & 15) * 4;
            int gm = m0 + mm;
            float4 v = (gm < MMP) ? *(const float4*)&ctx[((size_t)bh * MMP + gm) * DH_ + ee] : z4;
            *(float4*)&cs[mm][ee] = v;
        }
        // qp chunk: 32 rows x 64 m (float4)
        #pragma unroll
        for (int u = 0; u < 2; u++) {
            int f = t + u*256;          // float4 slots: 32*16
            int rr = f >> 4;
            int m4 = (f & 15) * 4;
            int gm = m0 + m4;
            float4 v = (gm < MMP) ? *(const float4*)&qpb[(size_t)rr * MMP + gm] : z4;
            *(float4*)&qs[rr][m4] = v;
        }
        __syncthreads();

        if (t < 32) {
            const int lim = (MMP - m0 < 64) ? (MMP - m0) : 64;
            float s = 0.f;
            for (int mm = 0; mm < lim; mm++) s += qs[t][mm] * ksb[m0 + mm];
            dsum[t] += s;
        }

        #pragma unroll 4
        for (int mm = 0; mm < 64; mm++) {
            float qv = qs[ri][mm];
            float4 c0 = *(const float4*)&cs[mm][e0];
            float4 c1 = *(const float4*)&cs[mm][e0 + 4];
            acc[0] += qv * c0.x; acc[1] += qv * c0.y;
            acc[2] += qv * c0.z; acc[3] += qv * c0.w;
            acc[4] += qv * c1.x; acc[5] += qv * c1.y;
            acc[6] += qv * c1.z; acc[7] += qv * c1.w;
        }
        __syncthreads();
    }

    const float dinv = 1.f / (dsum[ri] + 1e-8f);
    float* orow = out + ((size_t)(b * SEQ + n0 + ri) * H_ + h) * DH_ + e0;
    float4 o0 = make_float4(acc[0]*dinv, acc[1]*dinv, acc[2]*dinv, acc[3]*dinv);
    float4 o1 = make_float4(acc[4]*dinv, acc[5]*dinv, acc[6]*dinv, acc[7]*dinv);
    *(float4*)&orow[0] = o0;
    *(float4*)&orow[4] = o1;
}

// ---------------- GLU: a * sigmoid(g), float4 -------------------------------
__global__ void glu_kernel(const float* __restrict__ y, float* __restrict__ out)
{
    size_t idx = (size_t)blockIdx.x * 256 + threadIdx.x;  // float4 index, ROWS*INNER/4
    size_t row = idx >> 8;            // 256 float4 per row of INNER
    int c4 = (int)(idx & 255);
    const float4 a = ((const float4*)y)[row * 512 + c4];
    const float4 g = ((const float4*)y)[row * 512 + 256 + c4];
    float4 o;
    o.x = a.x / (1.f + expf(-g.x));
    o.y = a.y / (1.f + expf(-g.y));
    o.z = a.z / (1.f + expf(-g.z));
    o.w = a.w / (1.f + expf(-g.w));
    ((float4*)out)[idx] = o;
}

// ---------------- depthwise conv (K=31, pad 15) + SiLU, tiled ---------------
#define DC_CH 128
#define DC_TN 32
__global__ __launch_bounds__(256)
void dwconv2(const float* __restrict__ gin, const float* __restrict__ w,
             const float* __restrict__ bias, float* __restrict__ out)
{
    __shared__ float sin_[DC_TN + 30][DC_CH];
    __shared__ float sw[DC_CH * KW];

    const int c0 = blockIdx.x * DC_CH;
    const int n0 = blockIdx.y * DC_TN;
    const int b  = blockIdx.z;
    const int t  = threadIdx.x;

    // weights: 128*31 consecutive floats
    for (int i = t; i < DC_CH * KW; i += 256)
        sw[i] = w[(size_t)c0 * KW + i];
    // input tile: rows n0-15 .. n0+DC_TN+14
    #pragma unroll
    for (int u = 0; u < (DC_TN + 30) * DC_CH / 256; u++) {
        int f = t + u * 256;
        int rowi = f >> 7;        // 0..61
        int ch = f & 127;
        int n = n0 + rowi - 15;
        sin_[rowi][ch] = ((unsigned)n < SEQ)
            ? gin[((size_t)(b * SEQ + n) << 10) + c0 + ch] : 0.f;
    }
    __syncthreads();

    const int ch = t & 127;
    const int nl0 = (t >> 7) * 16;   // 0 or 16

    float wr[KW];
    #pragma unroll
    for (int k = 0; k < KW; k++) wr[k] = sw[ch * KW + k];
    const float bb = bias[c0 + ch];

    #pragma unroll
    for (int i = 0; i < 16; i++) {
        float acc = bb;
        #pragma unroll
        for (int k = 0; k < KW; k++)
            acc += sin_[nl0 + i + k][ch] * wr[k];
        float o = acc / (1.f + expf(-acc));
        out[((size_t)(b * SEQ + n0 + nl0 + i) << 10) + c0 + ch] = o;
    }
}

// ---------------- host orchestration ----------------------------------------
static inline void run_gemm(const float* A, const float* W, float* C,
                            const float* bias, const float* resid,
                            int Mdim, int Ndim, int Kdim, float alpha, int permute)
{
    dim3 grid((Ndim + 127) / 128, Mdim / 128);
    gemm_bf16x3<<<grid, 256>>>(A, W, C, bias, resid, Mdim, Ndim, Kdim, alpha, permute);
}

extern "C" void kernel_launch(void* const* d_in, const int* in_sizes, int n_in,
                              void* d_out, int out_size)
{
    const float* x    = (const float*)d_in[0];
    const float* ln1g = (const float*)d_in[1];
    const float* ln1b = (const float*)d_in[2];
    const float* wq   = (const float*)d_in[3];
    const float* bq   = (const float*)d_in[4];
    const float* wk   = (const float*)d_in[5];
    const float* bk   = (const float*)d_in[6];
    const float* wv   = (const float*)d_in[7];
    const float* bv   = (const float*)d_in[8];
    const float* wo   = (const float*)d_in[9];
    const float* bo   = (const float*)d_in[10];
    const float* proj = (const float*)d_in[11];
    const float* ln2g = (const float*)d_in[12];
    const float* ln2b = (const float*)d_in[13];
    const float* pw1w = (const float*)d_in[14];
    const float* pw1b = (const float*)d_in[15];
    const float* dww  = (const float*)d_in[16];
    const float* dwb  = (const float*)d_in[17];
    const float* pw2w = (const float*)d_in[18];
    const float* pw2b = (const float*)d_in[19];
    float* xo = (float*)d_out;

    float *h, *q, *k, *v, *qp, *kp, *ks, *part, *ctx, *att, *y, *glu, *dw;
    cudaGetSymbolAddress((void**)&h,    g_h);
    cudaGetSymbolAddress((void**)&q,    g_q);
    cudaGetSymbolAddress((void**)&k,    g_k);
    cudaGetSymbolAddress((void**)&v,    g_v);
    cudaGetSymbolAddress((void**)&qp,   g_qp);
    cudaGetSymbolAddress((void**)&kp,   g_kp);
    cudaGetSymbolAddress((void**)&ks,   g_ks);
    cudaGetSymbolAddress((void**)&part, g_part);
    cudaGetSymbolAddress((void**)&ctx,  g_ctx);
    cudaGetSymbolAddress((void**)&att,  g_att);
    cudaGetSymbolAddress((void**)&y,    g_y);
    cudaGetSymbolAddress((void**)&glu,  g_glu);
    cudaGetSymbolAddress((void**)&dw,   g_dw);

    cudaMemcpyAsync(xo, x, (size_t)ROWS * D_ * sizeof(float),
                    cudaMemcpyDeviceToDevice);

    const float dn    = (float)(1.0 / sqrt(sqrt(64.0)));   // 64^-0.25
    const float ratio = (float)(1.0 / sqrt(266.0));        // M^-0.5

    for (int l = 0; l < LNUM; l++) {
        // LN1
        ln_kernel<<<ROWS, 128>>>(xo, ln1g + (size_t)l*D_, ln1b + (size_t)l*D_, h);
        // QKV
        run_gemm(h, wq + (size_t)l*ID_*D_, q, bq + (size_t)l*ID_, nullptr, ROWS, ID_, D_, 1.f, 0);
        run_gemm(h, wk + (size_t)l*ID_*D_, k, bk + (size_t)l*ID_, nullptr, ROWS, ID_, D_, 1.f, 0);
        run_gemm(h, wv + (size_t)l*ID_*D_, v, bv + (size_t)l*ID_, nullptr, ROWS, ID_, D_, 1.f, 0);
        // FAVOR feature maps (permuted [bh][n][m] output), then exp postprocess
        run_gemm(q, proj + (size_t)l*MM*DH_, qp, nullptr, nullptr, RH, MM, DH_, dn, 1);
        run_gemm(k, proj + (size_t)l*MM*DH_, kp, nullptr, nullptr, RH, MM, DH_, dn, 1);
        {
            dim3 fg(SEQ / 8, NBH);
            favor_post2<<<fg, 256>>>(qp, q, 1, ratio);
            favor_post2<<<fg, 256>>>(kp, k, 0, ratio);
        }
        // linear attention
        {
            dim3 k1(8, NBH);
            ksum1<<<k1, 288>>>(kp, part);
            ksum2<<<NBH, 288>>>(part, ks);
            dim3 cg((MMP + 63) / 64, NBH);
            ctx_kernel<<<cg, 256>>>(kp, v, ctx);
            dim3 ag(SEQ / 32, NBH);
            attn_out2<<<ag, 256>>>(qp, ks, ctx, att);
        }
        // output projection + residual (in-place on xo)
        run_gemm(att, wo + (size_t)l*ID_*D_, xo, bo + (size_t)l*D_, xo, ROWS, D_, ID_, 1.f, 0);
        // LN2 + conv-FFN
        ln_kernel<<<ROWS, 128>>>(xo, ln2g + (size_t)l*D_, ln2b + (size_t)l*D_, h);
        run_gemm(h, pw1w + (size_t)l*2048*D_, y, pw1b + (size_t)l*2048, nullptr, ROWS, 2048, D_, 1.f, 0);
        glu_kernel<<<(ROWS*INNER_)/(256*4), 256>>>(y, glu);
        {
            dim3 dg(INNER_/DC_CH, SEQ/DC_TN, B_);
            dwconv2<<<dg, 256>>>(glu, dww + (size_t)l*INNER_*KW, dwb + (size_t)l*INNER_, dw);
        }
        run_gemm(dw, pw2w + (size_t)l*D_*INNER_, xo, pw2b + (size_t)l*D_, xo, ROWS, D_, INNER_, 1.f, 0);
    }
}